// round 8
// baseline (speedup 1.0000x reference)
#include <cuda_runtime.h>
#include <cuda_bf16.h>
#include <stdint.h>
#include <math.h>

#define NN 10000
#define NE 320000
#define DD 256
#define NL 3

typedef __nv_bfloat16 bf16;
typedef unsigned int uint;

// ---------------- scratch -----------------------------------------------------
__device__ float g_t[NN * DD];
__device__ bf16  g_xh[NN * DD], g_xl[NN * DD];          // x hi/lo, reused as agg hi/lo
__device__ bf16  g_hhA[NN * DD], g_hlA[NN * DD];
__device__ bf16  g_hhB[NN * DD], g_hlB[NN * DD];
__device__ bf16  g_winh[DD * DD], g_winl[DD * DD];
__device__ bf16  g_Mh[NL * DD * DD];                    // wq wk^T (bf16 hi)
__device__ bf16  g_Wh[NL * DD * DD];                    // wv wp   (bf16 hi)
__device__ int   g_deg[NN];
__device__ int   g_off[NN + 1];
__device__ int   g_cur[NN];
__device__ int   g_srcs[NE];

// ---------------- helpers -----------------------------------------------------
__device__ __forceinline__ void f32split(float v, bf16& h, bf16& l) {
    h = __float2bfloat16(v);
    l = __float2bfloat16(v - __bfloat162float(h));
}
__device__ __forceinline__ void ldsm4(uint& r0, uint& r1, uint& r2, uint& r3, uint addr) {
    asm volatile("ldmatrix.sync.aligned.m8n8.x4.shared.b16 {%0,%1,%2,%3}, [%4];"
                 : "=r"(r0), "=r"(r1), "=r"(r2), "=r"(r3) : "r"(addr));
}
__device__ __forceinline__ void ldsm4t(uint& r0, uint& r1, uint& r2, uint& r3, uint addr) {
    asm volatile("ldmatrix.sync.aligned.m8n8.x4.trans.shared.b16 {%0,%1,%2,%3}, [%4];"
                 : "=r"(r0), "=r"(r1), "=r"(r2), "=r"(r3) : "r"(addr));
}
__device__ __forceinline__ void mma_bf16(float* c, const uint* a, uint b0, uint b1) {
    asm volatile("mma.sync.aligned.m16n8k16.row.col.f32.bf16.bf16.f32 "
                 "{%0,%1,%2,%3},{%4,%5,%6,%7},{%8,%9},{%0,%1,%2,%3};"
                 : "+f"(c[0]), "+f"(c[1]), "+f"(c[2]), "+f"(c[3])
                 : "r"(a[0]), "r"(a[1]), "r"(a[2]), "r"(a[3]), "r"(b0), "r"(b1));
}
__device__ __forceinline__ void cp16(uint dst, const void* src) {
    asm volatile("cp.async.cg.shared.global [%0], [%1], 16;" :: "r"(dst), "l"(src));
}
__device__ __forceinline__ void cp16z(uint dst, const void* src, uint sz) {
    asm volatile("cp.async.cg.shared.global [%0], [%1], 16, %2;" :: "r"(dst), "l"(src), "r"(sz));
}
__device__ __forceinline__ void cp_commit() { asm volatile("cp.async.commit_group;"); }

// ---------------- CSR build ----------------------------------------------------
__global__ void k_init() {
    int i = blockIdx.x * blockDim.x + threadIdx.x;
    if (i < NN) { g_deg[i] = 0; g_cur[i] = 0; }
}
__global__ void k_hist(const int* __restrict__ dst) {
    int e = blockIdx.x * blockDim.x + threadIdx.x;
    if (e < NE) atomicAdd(&g_deg[dst[e]], 1);
}
__global__ void k_scan() {
    __shared__ int ws[32];
    int tid = threadIdx.x, lane = tid & 31, wid = tid >> 5;
    int carry = 0;
    for (int base = 0; base < NN; base += 1024) {
        int x = (base + tid < NN) ? g_deg[base + tid] : 0;
        int v = x;
        #pragma unroll
        for (int o = 1; o < 32; o <<= 1) {
            int y = __shfl_up_sync(0xffffffffu, v, o);
            if (lane >= o) v += y;
        }
        if (lane == 31) ws[wid] = v;
        __syncthreads();
        if (tid < 32) {
            int w = ws[tid];
            #pragma unroll
            for (int o = 1; o < 32; o <<= 1) {
                int y = __shfl_up_sync(0xffffffffu, w, o);
                if (tid >= o) w += y;
            }
            ws[tid] = w;
        }
        __syncthreads();
        int add = wid ? ws[wid - 1] : 0;
        if (base + tid < NN) g_off[base + tid] = carry + add + v - x;
        int tot = ws[31];
        __syncthreads();
        carry += tot;
    }
    if (tid == 0) g_off[NN] = carry;
}
__global__ void k_scatter(const int* __restrict__ src, const int* __restrict__ dst) {
    int e = blockIdx.x * blockDim.x + threadIdx.x;
    if (e < NE) {
        int d = dst[e];
        int pos = g_off[d] + atomicAdd(&g_cur[d], 1);
        g_srcs[pos] = src[e];
    }
}

// ---------------- fused fp32 -> bf16 hi/lo (x and w_in) -------------------------
__global__ void k_cvt2(const float* __restrict__ a, bf16* __restrict__ ah,
                       bf16* __restrict__ al, int na,
                       const float* __restrict__ b, bf16* __restrict__ bh,
                       bf16* __restrict__ bl, int nb) {
    int i = blockIdx.x * blockDim.x + threadIdx.x;
    if (i < na) {
        bf16 h, l; f32split(a[i], h, l); ah[i] = h; al[i] = l;
    } else if (i < na + nb) {
        int j = i - na;
        bf16 h, l; f32split(b[j], h, l); bh[j] = h; bl[j] = l;
    }
}

// ---------------- weight folding (bf16-hi outputs) -------------------------------
__global__ __launch_bounds__(256) void k_small(
    const float* __restrict__ wq, const float* __restrict__ wk,
    const float* __restrict__ wv, const float* __restrict__ wp,
    bf16* __restrict__ pMh, bf16* __restrict__ pWh)
{
    int z = blockIdx.z;
    const float* A; const float* B; bf16* Ch; int tb;
    if (z < 3) { A = wq + z * DD * DD; B = wk + z * DD * DD;
                 Ch = pMh + z * DD * DD; tb = 1; }
    else       { A = wv + (z - 3) * DD * DD; B = wp + (z - 3) * DD * DD;
                 Ch = pWh + (z - 3) * DD * DD; tb = 0; }

    __shared__ float As[16][65];
    __shared__ float Bs[16][65];
    int tid = threadIdx.x;
    int tx = tid & 15, ty = tid >> 4;
    int row0 = blockIdx.y * 64, col0 = blockIdx.x * 64;
    float acc[4][4] = {};

    for (int kt = 0; kt < DD; kt += 16) {
        {
            int r = tid >> 2, c = (tid & 3) * 4;
            float4 v = *(const float4*)(A + (row0 + r) * DD + kt + c);
            As[c + 0][r] = v.x; As[c + 1][r] = v.y; As[c + 2][r] = v.z; As[c + 3][r] = v.w;
        }
        if (tb) {
            int c = tid >> 2, k = (tid & 3) * 4;
            float4 v = *(const float4*)(B + (col0 + c) * DD + kt + k);
            Bs[k + 0][c] = v.x; Bs[k + 1][c] = v.y; Bs[k + 2][c] = v.z; Bs[k + 3][c] = v.w;
        } else {
            int k = tid >> 4, c = (tid & 15) * 4;
            float4 v = *(const float4*)(B + (kt + k) * DD + col0 + c);
            Bs[k][c + 0] = v.x; Bs[k][c + 1] = v.y; Bs[k][c + 2] = v.z; Bs[k][c + 3] = v.w;
        }
        __syncthreads();
        #pragma unroll
        for (int kk = 0; kk < 16; kk++) {
            float a[4], b[4];
            #pragma unroll
            for (int i = 0; i < 4; i++) { a[i] = As[kk][ty * 4 + i]; b[i] = Bs[kk][tx * 4 + i]; }
            #pragma unroll
            for (int i = 0; i < 4; i++)
                #pragma unroll
                for (int j = 0; j < 4; j++)
                    acc[i][j] += a[i] * b[j];
        }
        __syncthreads();
    }
    #pragma unroll
    for (int i = 0; i < 4; i++)
        #pragma unroll
        for (int j = 0; j < 4; j++)
            Ch[(row0 + ty * 4 + i) * DD + col0 + tx * 4 + j] = __float2bfloat16(acc[i][j]);
}

// ---------------- h0 GEMM (HMMA, full hi/lo precision) --------------------------
#define ST1_ELEMS 18944
#define A_PITCH 40
#define B_PITCH 136

__global__ __launch_bounds__(256, 1) void k_mma_h0(
    const bf16* __restrict__ Ah, const bf16* __restrict__ Al,
    const bf16* __restrict__ Bh, const bf16* __restrict__ Bl,
    const float* __restrict__ bias,
    bf16* __restrict__ Chi, bf16* __restrict__ Clo)
{
    extern __shared__ __align__(16) bf16 smem[];
    int tid = threadIdx.x;
    int lane = tid & 31, warp = tid >> 5;
    int wm = warp & 1, wn = warp >> 1;
    int row0 = blockIdx.y * 128, col0 = blockIdx.x * 128;

    uint sbase = (uint)__cvta_generic_to_shared(smem);
    int a_r0 = tid >> 2,        a_c0 = (tid & 3) * 8;
    int a_r1 = (tid + 256) >> 2;
    int b_r0 = tid >> 4,        b_c0 = (tid & 15) * 8;
    int b_r1 = (tid + 256) >> 4;

    int ga0 = row0 + a_r0, ga1 = row0 + a_r1;
    uint sz0 = (ga0 < NN) ? 16u : 0u;
    uint sz1 = (ga1 < NN) ? 16u : 0u;
    int ca0 = (ga0 < NN) ? ga0 : 0;
    int ca1 = (ga1 < NN) ? ga1 : 0;

    auto issue = [&](int st, int kt) {
        uint base = sbase + (uint)(st * ST1_ELEMS) * 2u;
        uint dA0 = base + (uint)(a_r0 * A_PITCH + a_c0) * 2u;
        uint dA1 = base + (uint)(a_r1 * A_PITCH + a_c0) * 2u;
        cp16z(dA0,            Ah + (size_t)ca0 * DD + kt + a_c0, sz0);
        cp16z(dA1,            Ah + (size_t)ca1 * DD + kt + a_c0, sz1);
        cp16z(dA0 + 5120u*2u, Al + (size_t)ca0 * DD + kt + a_c0, sz0);
        cp16z(dA1 + 5120u*2u, Al + (size_t)ca1 * DD + kt + a_c0, sz1);
        uint dB0 = base + (10240u + (uint)(b_r0 * B_PITCH + b_c0)) * 2u;
        uint dB1 = base + (10240u + (uint)(b_r1 * B_PITCH + b_c0)) * 2u;
        cp16(dB0, Bh + (size_t)(kt + b_r0) * DD + col0 + b_c0);
        cp16(dB1, Bh + (size_t)(kt + b_r1) * DD + col0 + b_c0);
        cp16(dB0 + 4352u*2u, Bl + (size_t)(kt + b_r0) * DD + col0 + b_c0);
        cp16(dB1 + 4352u*2u, Bl + (size_t)(kt + b_r1) * DD + col0 + b_c0);
    };

    float acc[4][4][4] = {};
    issue(0, 0);   cp_commit();
    issue(1, 32);  cp_commit();

    #pragma unroll
    for (int i = 0; i < 8; i++) {
        if (i < 7) asm volatile("cp.async.wait_group 1;");
        else       asm volatile("cp.async.wait_group 0;");
        __syncthreads();
        if (i < 6) { issue((i + 2) % 3, (i + 2) * 32); cp_commit(); }

        int st = i % 3;
        uint base = sbase + (uint)(st * ST1_ELEMS) * 2u;
        uint aAh = base, aAl = base + 5120u * 2u;
        uint aBh = base + 10240u * 2u, aBl = base + 14592u * 2u;

        #pragma unroll
        for (int ks = 0; ks < 32; ks += 16) {
            int arow = lane & 15;
            int kcol = ks + ((lane >> 4) << 3);
            uint ah[4][4], al[4][4];
            #pragma unroll
            for (int mi = 0; mi < 4; mi++) {
                uint off = (uint)((wm * 64 + mi * 16 + arow) * A_PITCH + kcol) * 2u;
                ldsm4(ah[mi][0], ah[mi][1], ah[mi][2], ah[mi][3], aAh + off);
                ldsm4(al[mi][0], al[mi][1], al[mi][2], al[mi][3], aAl + off);
            }
            uint bhf[2][4], blf[2][4];
            int brow = ks + (lane & 15);
            #pragma unroll
            for (int ng = 0; ng < 2; ng++) {
                int bcol = wn * 32 + ng * 16 + ((lane >> 4) << 3);
                uint off = (uint)(brow * B_PITCH + bcol) * 2u;
                ldsm4t(bhf[ng][0], bhf[ng][1], bhf[ng][2], bhf[ng][3], aBh + off);
                ldsm4t(blf[ng][0], blf[ng][1], blf[ng][2], blf[ng][3], aBl + off);
            }
            #pragma unroll
            for (int mi = 0; mi < 4; mi++)
                #pragma unroll
                for (int ng = 0; ng < 2; ng++) {
                    mma_bf16(acc[mi][ng * 2],     ah[mi], bhf[ng][0], bhf[ng][1]);
                    mma_bf16(acc[mi][ng * 2 + 1], ah[mi], bhf[ng][2], bhf[ng][3]);
                }
            #pragma unroll
            for (int mi = 0; mi < 4; mi++)
                #pragma unroll
                for (int ng = 0; ng < 2; ng++) {
                    mma_bf16(acc[mi][ng * 2],     al[mi], bhf[ng][0], bhf[ng][1]);
                    mma_bf16(acc[mi][ng * 2 + 1], al[mi], bhf[ng][2], bhf[ng][3]);
                }
            #pragma unroll
            for (int mi = 0; mi < 4; mi++)
                #pragma unroll
                for (int ng = 0; ng < 2; ng++) {
                    mma_bf16(acc[mi][ng * 2],     ah[mi], blf[ng][0], blf[ng][1]);
                    mma_bf16(acc[mi][ng * 2 + 1], ah[mi], blf[ng][2], blf[ng][3]);
                }
        }
    }

    int grp = lane >> 2, q = lane & 3;
    #pragma unroll
    for (int mi = 0; mi < 4; mi++) {
        int rb = row0 + wm * 64 + mi * 16 + grp;
        #pragma unroll
        for (int nj = 0; nj < 4; nj++) {
            int cb = col0 + wn * 32 + nj * 8 + q * 2;
            float b0 = bias[cb], b1 = bias[cb + 1];
            float v0 = fmaxf(acc[mi][nj][0] + b0, 0.f);
            float v1 = fmaxf(acc[mi][nj][1] + b1, 0.f);
            float v2 = fmaxf(acc[mi][nj][2] + b0, 0.f);
            float v3 = fmaxf(acc[mi][nj][3] + b1, 0.f);
            if (rb < NN) {
                size_t o = (size_t)rb * DD + cb;
                bf16 h0, l0, h1, l1;
                f32split(v0, h0, l0); f32split(v1, h1, l1);
                Chi[o] = h0; Chi[o + 1] = h1;
                Clo[o] = l0; Clo[o + 1] = l1;
            }
            if (rb + 8 < NN) {
                size_t o = (size_t)(rb + 8) * DD + cb;
                bf16 h2, l2, h3, l3;
                f32split(v2, h2, l2); f32split(v3, h3, l3);
                Chi[o] = h2; Chi[o + 1] = h3;
                Clo[o] = l2; Clo[o + 1] = l3;
            }
        }
    }
}

// ---------------- unified 2-product GEMM (t-mode / p-mode) ----------------------
// C = (Ah+Al) @ Bh.  t-mode: store fp32 to f32_out.
// p-mode: v = acc + bias + (rhh+rhl); relu; store fp32 (final) and/or bf16 hi/lo.
#define STU_ELEMS 14592

__global__ __launch_bounds__(256, 2) void k_gemm(
    const bf16* __restrict__ Ah, const bf16* __restrict__ Al,
    const bf16* __restrict__ Bh,
    float* __restrict__ f32_out, const float* __restrict__ bias,
    const bf16* __restrict__ rhh, const bf16* __restrict__ rhl,
    bf16* __restrict__ Chi, bf16* __restrict__ Clo)
{
    extern __shared__ __align__(16) bf16 smem[];
    int col0 = blockIdx.x * 128;
    int row0 = blockIdx.y * 128;

    int tid = threadIdx.x;
    int lane = tid & 31, warp = tid >> 5;
    int wm = warp & 1, wn = warp >> 1;

    uint sbase = (uint)__cvta_generic_to_shared(smem);
    int a_r0 = tid >> 2,        a_c0 = (tid & 3) * 8;
    int a_r1 = (tid + 256) >> 2;
    int b_r0 = tid >> 4,        b_c0 = (tid & 15) * 8;
    int b_r1 = (tid + 256) >> 4;

    int ga0 = row0 + a_r0, ga1 = row0 + a_r1;
    uint sz0 = (ga0 < NN) ? 16u : 0u;
    uint sz1 = (ga1 < NN) ? 16u : 0u;
    int ca0 = (ga0 < NN) ? ga0 : 0;
    int ca1 = (ga1 < NN) ? ga1 : 0;

    auto issue = [&](int st, int kt) {
        uint base = sbase + (uint)(st * STU_ELEMS) * 2u;
        uint dA0 = base + (uint)(a_r0 * A_PITCH + a_c0) * 2u;
        uint dA1 = base + (uint)(a_r1 * A_PITCH + a_c0) * 2u;
        cp16z(dA0,            Ah + (size_t)ca0 * DD + kt + a_c0, sz0);
        cp16z(dA1,            Ah + (size_t)ca1 * DD + kt + a_c0, sz1);
        cp16z(dA0 + 5120u*2u, Al + (size_t)ca0 * DD + kt + a_c0, sz0);
        cp16z(dA1 + 5120u*2u, Al + (size_t)ca1 * DD + kt + a_c0, sz1);
        uint dB0 = base + (10240u + (uint)(b_r0 * B_PITCH + b_c0)) * 2u;
        uint dB1 = base + (10240u + (uint)(b_r1 * B_PITCH + b_c0)) * 2u;
        cp16(dB0, Bh + (size_t)(kt + b_r0) * DD + col0 + b_c0);
        cp16(dB1, Bh + (size_t)(kt + b_r1) * DD + col0 + b_c0);
    };

    float acc[4][4][4] = {};
    issue(0, 0);   cp_commit();
    issue(1, 32);  cp_commit();

    #pragma unroll
    for (int i = 0; i < 8; i++) {
        if (i < 7) asm volatile("cp.async.wait_group 1;");
        else       asm volatile("cp.async.wait_group 0;");
        __syncthreads();
        if (i < 6) { issue((i + 2) % 3, (i + 2) * 32); cp_commit(); }

        int st = i % 3;
        uint base = sbase + (uint)(st * STU_ELEMS) * 2u;
        uint aAh = base, aAl = base + 5120u * 2u;
        uint aBh = base + 10240u * 2u;

        #pragma unroll
        for (int ks = 0; ks < 32; ks += 16) {
            int arow = lane & 15;
            int kcol = ks + ((lane >> 4) << 3);
            uint ah[4][4], al[4][4];
            #pragma unroll
            for (int mi = 0; mi < 4; mi++) {
                uint off = (uint)((wm * 64 + mi * 16 + arow) * A_PITCH + kcol) * 2u;
                ldsm4(ah[mi][0], ah[mi][1], ah[mi][2], ah[mi][3], aAh + off);
                ldsm4(al[mi][0], al[mi][1], al[mi][2], al[mi][3], aAl + off);
            }
            uint bhf[2][4];
            int brow = ks + (lane & 15);
            #pragma unroll
            for (int ng = 0; ng < 2; ng++) {
                int bcol = wn * 32 + ng * 16 + ((lane >> 4) << 3);
                uint off = (uint)(brow * B_PITCH + bcol) * 2u;
                ldsm4t(bhf[ng][0], bhf[ng][1], bhf[ng][2], bhf[ng][3], aBh + off);
            }
            #pragma unroll
            for (int mi = 0; mi < 4; mi++)
                #pragma unroll
                for (int ng = 0; ng < 2; ng++) {
                    mma_bf16(acc[mi][ng * 2],     ah[mi], bhf[ng][0], bhf[ng][1]);
                    mma_bf16(acc[mi][ng * 2 + 1], ah[mi], bhf[ng][2], bhf[ng][3]);
                }
            #pragma unroll
            for (int mi = 0; mi < 4; mi++)
                #pragma unroll
                for (int ng = 0; ng < 2; ng++) {
                    mma_bf16(acc[mi][ng * 2],     al[mi], bhf[ng][0], bhf[ng][1]);
                    mma_bf16(acc[mi][ng * 2 + 1], al[mi], bhf[ng][2], bhf[ng][3]);
                }
        }
    }

    int grp = lane >> 2, q = lane & 3;
    #pragma unroll
    for (int mi = 0; mi < 4; mi++) {
        int rb = row0 + wm * 64 + mi * 16 + grp;
        #pragma unroll
        for (int nj = 0; nj < 4; nj++) {
            int cb = col0 + wn * 32 + nj * 8 + q * 2;
            float v0 = acc[mi][nj][0], v1 = acc[mi][nj][1];
            float v2 = acc[mi][nj][2], v3 = acc[mi][nj][3];
            if (bias) {
                float b0 = bias[cb], b1 = bias[cb + 1];
                size_t o0 = (size_t)rb * DD + cb;
                size_t o1 = (size_t)(rb + 8) * DD + cb;
                float r00 = 0.f, r01 = 0.f, r10 = 0.f, r11 = 0.f;
                if (rb < NN) {
                    r00 = __bfloat162float(rhh[o0])     + __bfloat162float(rhl[o0]);
                    r01 = __bfloat162float(rhh[o0 + 1]) + __bfloat162float(rhl[o0 + 1]);
                }
                if (rb + 8 < NN) {
                    r10 = __bfloat162float(rhh[o1])     + __bfloat162float(rhl[o1]);
                    r11 = __bfloat162float(rhh[o1 + 1]) + __bfloat162float(rhl[o1 + 1]);
                }
                v0 = fmaxf(v0 + b0 + r00, 0.f);
                v1 = fmaxf(v1 + b1 + r01, 0.f);
                v2 = fmaxf(v2 + b0 + r10, 0.f);
                v3 = fmaxf(v3 + b1 + r11, 0.f);
            }
            if (rb < NN) {
                size_t o = (size_t)rb * DD + cb;
                if (f32_out) { f32_out[o] = v0; f32_out[o + 1] = v1; }
                if (Chi) {
                    bf16 h0, l0, h1, l1;
                    f32split(v0, h0, l0); f32split(v1, h1, l1);
                    Chi[o] = h0; Chi[o + 1] = h1;
                    Clo[o] = l0; Clo[o + 1] = l1;
                }
            }
            if (rb + 8 < NN) {
                size_t o = (size_t)(rb + 8) * DD + cb;
                if (f32_out) { f32_out[o] = v2; f32_out[o + 1] = v3; }
                if (Chi) {
                    bf16 h2, l2, h3, l3;
                    f32split(v2, h2, l2); f32split(v3, h3, l3);
                    Chi[o] = h2; Chi[o + 1] = h3;
                    Clo[o] = l2; Clo[o + 1] = l3;
                }
            }
        }
    }
}

// ---------------- per-node online-softmax h-aggregation -------------------------
// agg_h[n] = sum_e softmax(t[n].h_src/16) * h_src; output exact bf16 hi/lo split.
__global__ __launch_bounds__(256) void k_edge(
    const bf16* __restrict__ hhin,
    bf16* __restrict__ agg_hi, bf16* __restrict__ agg_lo)
{
    int gw = (blockIdx.x * blockDim.x + threadIdx.x) >> 5;
    int lane = threadIdx.x & 31;
    if (gw >= NN) return;
    int n = gw;
    int c0 = lane * 8;

    float t8[8];
    *(float4*)&t8[0] = *(const float4*)(g_t + (size_t)n * DD + c0);
    *(float4*)&t8[4] = *(const float4*)(g_t + (size_t)n * DD + c0 + 4);

    float m = -INFINITY, s = 0.f;
    float acc[8] = {};

    int e0 = g_off[n], e1 = g_off[n + 1];
    uint4 hv0, hv1;
    if (e0 < e1) {
        int sN = g_srcs[e0];
        hv0 = *(const uint4*)(hhin + (size_t)sN * DD + c0);
    }
    if (e0 + 1 < e1) {
        int sN = g_srcs[e0 + 1];
        hv1 = *(const uint4*)(hhin + (size_t)sN * DD + c0);
    }
    for (int e = e0; e < e1; e++) {
        uint4 hv = hv0;
        hv0 = hv1;
        if (e + 2 < e1) {
            int sN = g_srcs[e + 2];
            hv1 = *(const uint4*)(hhin + (size_t)sN * DD + c0);
        }

        const __nv_bfloat162* hp = (const __nv_bfloat162*)&hv;
        float hf[8];
        #pragma unroll
        for (int j = 0; j < 4; j++) {
            float2 f = __bfloat1622float2(hp[j]);
            hf[2 * j] = f.x; hf[2 * j + 1] = f.y;
        }
        float d = 0.f;
        #pragma unroll
        for (int j = 0; j < 8; j++) d += t8[j] * hf[j];
        #pragma unroll
        for (int o = 16; o > 0; o >>= 1) d += __shfl_xor_sync(0xffffffffu, d, o);
        d *= 0.0625f;

        float nm = fmaxf(m, d);
        float c = __expf(m - nm);
        float w = __expf(d - nm);
        s = s * c + w;
        m = nm;

        #pragma unroll
        for (int j = 0; j < 8; j++)
            acc[j] = acc[j] * c + w * hf[j];
    }

    float inv = 1.0f / (s + 1e-9f);
    bf16 hh8[8], hl8[8];
    #pragma unroll
    for (int j = 0; j < 8; j++) f32split(acc[j] * inv, hh8[j], hl8[j]);
    *(uint4*)(agg_hi + (size_t)n * DD + c0) = *(uint4*)&hh8[0];
    *(uint4*)(agg_lo + (size_t)n * DD + c0) = *(uint4*)&hl8[0];
}

// ---------------- launch ----------------------------------------------------------
extern "C" void kernel_launch(void* const* d_in, const int* in_sizes, int n_in,
                              void* d_out, int out_size)
{
    const float* x    = (const float*)d_in[0];
    const int*   edges= (const int*)  d_in[1];
    const float* w_in = (const float*)d_in[2];
    const float* b_in = (const float*)d_in[3];
    const float* wq   = (const float*)d_in[4];
    const float* wk   = (const float*)d_in[5];
    const float* wv   = (const float*)d_in[6];
    const float* wp   = (const float*)d_in[7];
    const float* bp   = (const float*)d_in[8];
    float* out = (float*)d_out;

    const int* src = edges;
    const int* dst = edges + NE;

    float *pt;
    bf16 *pxh, *pxl, *phhA, *phlA, *phhB, *phlB, *pwinh, *pwinl, *pMh, *pWh;
    cudaGetSymbolAddress((void**)&pt,    g_t);
    cudaGetSymbolAddress((void**)&pxh,   g_xh);
    cudaGetSymbolAddress((void**)&pxl,   g_xl);
    cudaGetSymbolAddress((void**)&phhA,  g_hhA);
    cudaGetSymbolAddress((void**)&phlA,  g_hlA);
    cudaGetSymbolAddress((void**)&phhB,  g_hhB);
    cudaGetSymbolAddress((void**)&phlB,  g_hlB);
    cudaGetSymbolAddress((void**)&pwinh, g_winh);
    cudaGetSymbolAddress((void**)&pwinl, g_winl);
    cudaGetSymbolAddress((void**)&pMh,   g_Mh);
    cudaGetSymbolAddress((void**)&pWh,   g_Wh);

    static bool attr_set = false;
    if (!attr_set) {
        cudaFuncSetAttribute(k_mma_h0, cudaFuncAttributeMaxDynamicSharedMemorySize,
                             3 * ST1_ELEMS * 2);
        cudaFuncSetAttribute(k_gemm, cudaFuncAttributeMaxDynamicSharedMemorySize,
                             3 * STU_ELEMS * 2);
        attr_set = true;
    }

    // 1: fused conversions
    k_cvt2<<<(NN * DD + DD * DD + 255) / 256, 256>>>(
        x, pxh, pxl, NN * DD, w_in, pwinh, pwinl, DD * DD);
    // 2: weight folding
    k_small<<<dim3(4, 4, 6), 256>>>(wq, wk, wv, wp, pMh, pWh);
    // 3: h0 = relu(x @ w_in + b_in)
    k_mma_h0<<<dim3(2, 79), 256, 3 * ST1_ELEMS * 2>>>(
        pxh, pxl, pwinh, pwinl, b_in, phhA, phlA);
    // 4: layer-0 t GEMM (profiled slot)
    k_gemm<<<dim3(2, 79), 256, 3 * STU_ELEMS * 2>>>(
        phhA, phlA, pMh, pt, nullptr, nullptr, nullptr, nullptr, nullptr);

    // CSR build
    k_init   <<<(NN + 255) / 256, 256>>>();
    k_hist   <<<(NE + 255) / 256, 256>>>(dst);
    k_scan   <<<1, 1024>>>();
    k_scatter<<<(NE + 255) / 256, 256>>>(src, dst);

    // agg buffers reuse x hi/lo (h0 already consumed them)
    bf16* paggh = pxh;
    bf16* paggl = pxl;

    bf16* chh = phhA; bf16* chl = phlA;
    bf16* nhh = phhB; bf16* nhl = phlB;
    for (int l = 0; l < NL; l++) {
        if (l > 0)
            k_gemm<<<dim3(2, 79), 256, 3 * STU_ELEMS * 2>>>(
                chh, chl, pMh + l * DD * DD, pt,
                nullptr, nullptr, nullptr, nullptr, nullptr);
        // edge: aggregate h with softmax weights
        k_edge<<<(NN * 32 + 255) / 256, 256>>>(chh, paggh, paggl);
        // p GEMM: hnext = relu(agg @ wvp + bp + h)
        float* ho = (l == NL - 1) ? out : nullptr;
        bf16* oh = (l == NL - 1) ? nullptr : nhh;
        bf16* ol = (l == NL - 1) ? nullptr : nhl;
        k_gemm<<<dim3(2, 79), 256, 3 * STU_ELEMS * 2>>>(
            paggh, paggl, pWh + l * DD * DD, ho,
            bp + l * DD, chh, chl, oh, ol);
        bf16* t1 = chh; chh = nhh; nhh = t1;
        bf16* t2 = chl; chl = nhl; nhl = t2;
    }
}

// round 9
// speedup vs baseline: 1.1519x; 1.1519x over previous
#include <cuda_runtime.h>
#include <cuda_bf16.h>
#include <stdint.h>
#include <math.h>

#define NN 10000
#define NE 320000
#define DD 256
#define NL 3

typedef __nv_bfloat16 bf16;
typedef unsigned int uint;

// ---------------- scratch -----------------------------------------------------
__device__ float g_t[NN * DD];
__device__ bf16  g_xh[NN * DD], g_xl[NN * DD];          // x hi/lo, reused as agg hi/lo
__device__ bf16  g_hhA[NN * DD], g_hlA[NN * DD];
__device__ bf16  g_hhB[NN * DD], g_hlB[NN * DD];
__device__ bf16  g_winh[DD * DD], g_winl[DD * DD];
__device__ bf16  g_Mh[NL * DD * DD];                    // wq wk^T (bf16 hi)
__device__ bf16  g_Wh[NL * DD * DD];                    // wv wp   (bf16 hi)
__device__ int   g_deg[NN];
__device__ int   g_off[NN + 1];
__device__ int   g_cur[NN];
__device__ int   g_srcs[NE];

// ---------------- helpers -----------------------------------------------------
__device__ __forceinline__ void f32split(float v, bf16& h, bf16& l) {
    h = __float2bfloat16(v);
    l = __float2bfloat16(v - __bfloat162float(h));
}
__device__ __forceinline__ void ldsm4(uint& r0, uint& r1, uint& r2, uint& r3, uint addr) {
    asm volatile("ldmatrix.sync.aligned.m8n8.x4.shared.b16 {%0,%1,%2,%3}, [%4];"
                 : "=r"(r0), "=r"(r1), "=r"(r2), "=r"(r3) : "r"(addr));
}
__device__ __forceinline__ void ldsm4t(uint& r0, uint& r1, uint& r2, uint& r3, uint addr) {
    asm volatile("ldmatrix.sync.aligned.m8n8.x4.trans.shared.b16 {%0,%1,%2,%3}, [%4];"
                 : "=r"(r0), "=r"(r1), "=r"(r2), "=r"(r3) : "r"(addr));
}
__device__ __forceinline__ void mma_bf16(float* c, const uint* a, uint b0, uint b1) {
    asm volatile("mma.sync.aligned.m16n8k16.row.col.f32.bf16.bf16.f32 "
                 "{%0,%1,%2,%3},{%4,%5,%6,%7},{%8,%9},{%0,%1,%2,%3};"
                 : "+f"(c[0]), "+f"(c[1]), "+f"(c[2]), "+f"(c[3])
                 : "r"(a[0]), "r"(a[1]), "r"(a[2]), "r"(a[3]), "r"(b0), "r"(b1));
}
__device__ __forceinline__ void cp16(uint dst, const void* src) {
    asm volatile("cp.async.cg.shared.global [%0], [%1], 16;" :: "r"(dst), "l"(src));
}
__device__ __forceinline__ void cp16z(uint dst, const void* src, uint sz) {
    asm volatile("cp.async.cg.shared.global [%0], [%1], 16, %2;" :: "r"(dst), "l"(src), "r"(sz));
}
__device__ __forceinline__ void cp_commit() { asm volatile("cp.async.commit_group;"); }

// ---------------- CSR build ----------------------------------------------------
__global__ void k_init() {
    int i = blockIdx.x * blockDim.x + threadIdx.x;
    if (i < NN) { g_deg[i] = 0; g_cur[i] = 0; }
}
__global__ void k_hist(const int* __restrict__ dst) {
    int e = blockIdx.x * blockDim.x + threadIdx.x;
    if (e < NE) atomicAdd(&g_deg[dst[e]], 1);
}
__global__ void k_scan() {
    __shared__ int ws[32];
    int tid = threadIdx.x, lane = tid & 31, wid = tid >> 5;
    int carry = 0;
    for (int base = 0; base < NN; base += 1024) {
        int x = (base + tid < NN) ? g_deg[base + tid] : 0;
        int v = x;
        #pragma unroll
        for (int o = 1; o < 32; o <<= 1) {
            int y = __shfl_up_sync(0xffffffffu, v, o);
            if (lane >= o) v += y;
        }
        if (lane == 31) ws[wid] = v;
        __syncthreads();
        if (tid < 32) {
            int w = ws[tid];
            #pragma unroll
            for (int o = 1; o < 32; o <<= 1) {
                int y = __shfl_up_sync(0xffffffffu, w, o);
                if (tid >= o) w += y;
            }
            ws[tid] = w;
        }
        __syncthreads();
        int add = wid ? ws[wid - 1] : 0;
        if (base + tid < NN) g_off[base + tid] = carry + add + v - x;
        int tot = ws[31];
        __syncthreads();
        carry += tot;
    }
    if (tid == 0) g_off[NN] = carry;
}
__global__ void k_scatter(const int* __restrict__ src, const int* __restrict__ dst) {
    int e = blockIdx.x * blockDim.x + threadIdx.x;
    if (e < NE) {
        int d = dst[e];
        int pos = g_off[d] + atomicAdd(&g_cur[d], 1);
        g_srcs[pos] = src[e];
    }
}

// ---------------- fused fp32 -> bf16 hi/lo (x and w_in) -------------------------
__global__ void k_cvt2(const float* __restrict__ a, bf16* __restrict__ ah,
                       bf16* __restrict__ al, int na,
                       const float* __restrict__ b, bf16* __restrict__ bh,
                       bf16* __restrict__ bl, int nb) {
    int i = blockIdx.x * blockDim.x + threadIdx.x;
    if (i < na) {
        bf16 h, l; f32split(a[i], h, l); ah[i] = h; al[i] = l;
    } else if (i < na + nb) {
        int j = i - na;
        bf16 h, l; f32split(b[j], h, l); bh[j] = h; bl[j] = l;
    }
}

// ---------------- weight folding (bf16-hi outputs) -------------------------------
__global__ __launch_bounds__(256) void k_small(
    const float* __restrict__ wq, const float* __restrict__ wk,
    const float* __restrict__ wv, const float* __restrict__ wp,
    bf16* __restrict__ pMh, bf16* __restrict__ pWh)
{
    int z = blockIdx.z;
    const float* A; const float* B; bf16* Ch; int tb;
    if (z < 3) { A = wq + z * DD * DD; B = wk + z * DD * DD;
                 Ch = pMh + z * DD * DD; tb = 1; }
    else       { A = wv + (z - 3) * DD * DD; B = wp + (z - 3) * DD * DD;
                 Ch = pWh + (z - 3) * DD * DD; tb = 0; }

    __shared__ float As[16][65];
    __shared__ float Bs[16][65];
    int tid = threadIdx.x;
    int tx = tid & 15, ty = tid >> 4;
    int row0 = blockIdx.y * 64, col0 = blockIdx.x * 64;
    float acc[4][4] = {};

    for (int kt = 0; kt < DD; kt += 16) {
        {
            int r = tid >> 2, c = (tid & 3) * 4;
            float4 v = *(const float4*)(A + (row0 + r) * DD + kt + c);
            As[c + 0][r] = v.x; As[c + 1][r] = v.y; As[c + 2][r] = v.z; As[c + 3][r] = v.w;
        }
        if (tb) {
            int c = tid >> 2, k = (tid & 3) * 4;
            float4 v = *(const float4*)(B + (col0 + c) * DD + kt + k);
            Bs[k + 0][c] = v.x; Bs[k + 1][c] = v.y; Bs[k + 2][c] = v.z; Bs[k + 3][c] = v.w;
        } else {
            int k = tid >> 4, c = (tid & 15) * 4;
            float4 v = *(const float4*)(B + (kt + k) * DD + col0 + c);
            Bs[k][c + 0] = v.x; Bs[k][c + 1] = v.y; Bs[k][c + 2] = v.z; Bs[k][c + 3] = v.w;
        }
        __syncthreads();
        #pragma unroll
        for (int kk = 0; kk < 16; kk++) {
            float a[4], b[4];
            #pragma unroll
            for (int i = 0; i < 4; i++) { a[i] = As[kk][ty * 4 + i]; b[i] = Bs[kk][tx * 4 + i]; }
            #pragma unroll
            for (int i = 0; i < 4; i++)
                #pragma unroll
                for (int j = 0; j < 4; j++)
                    acc[i][j] += a[i] * b[j];
        }
        __syncthreads();
    }
    #pragma unroll
    for (int i = 0; i < 4; i++)
        #pragma unroll
        for (int j = 0; j < 4; j++)
            Ch[(row0 + ty * 4 + i) * DD + col0 + tx * 4 + j] = __float2bfloat16(acc[i][j]);
}

// ---------------- h0 GEMM: 64x128 tile, 3 products, occ 2 -----------------------
// stage elems: Ah@0 (64x40), Al@2560, Bh@5120 (32x136), Bl@9472; total 13824
#define STH_ELEMS 13824
#define A_PITCH 40
#define B_PITCH 136

__global__ __launch_bounds__(256, 2) void k_mma_h0(
    const bf16* __restrict__ Ah, const bf16* __restrict__ Al,
    const bf16* __restrict__ Bh, const bf16* __restrict__ Bl,
    const float* __restrict__ bias,
    bf16* __restrict__ Chi, bf16* __restrict__ Clo)
{
    extern __shared__ __align__(16) bf16 smem[];
    int tid = threadIdx.x;
    int lane = tid & 31, warp = tid >> 5;
    int wm = warp & 1, wn = warp >> 1;      // 2 M-warps (32 rows) x 4 N-warps (32 cols)
    int row0 = blockIdx.y * 64, col0 = blockIdx.x * 128;

    uint sbase = (uint)__cvta_generic_to_shared(smem);
    int a_r0 = tid >> 2,        a_c0 = (tid & 3) * 8;     // 256 chunks cover 64x32
    int b_r0 = tid >> 4,        b_c0 = (tid & 15) * 8;
    int b_r1 = (tid + 256) >> 4;

    int ga0 = row0 + a_r0;
    uint sz0 = (ga0 < NN) ? 16u : 0u;
    int ca0 = (ga0 < NN) ? ga0 : 0;

    auto issue = [&](int st, int kt) {
        uint base = sbase + (uint)(st * STH_ELEMS) * 2u;
        uint dA0 = base + (uint)(a_r0 * A_PITCH + a_c0) * 2u;
        cp16z(dA0,            Ah + (size_t)ca0 * DD + kt + a_c0, sz0);
        cp16z(dA0 + 2560u*2u, Al + (size_t)ca0 * DD + kt + a_c0, sz0);
        uint dB0 = base + (5120u + (uint)(b_r0 * B_PITCH + b_c0)) * 2u;
        uint dB1 = base + (5120u + (uint)(b_r1 * B_PITCH + b_c0)) * 2u;
        cp16(dB0, Bh + (size_t)(kt + b_r0) * DD + col0 + b_c0);
        cp16(dB1, Bh + (size_t)(kt + b_r1) * DD + col0 + b_c0);
        cp16(dB0 + 4352u*2u, Bl + (size_t)(kt + b_r0) * DD + col0 + b_c0);
        cp16(dB1 + 4352u*2u, Bl + (size_t)(kt + b_r1) * DD + col0 + b_c0);
    };

    float acc[2][4][4] = {};
    issue(0, 0);   cp_commit();
    issue(1, 32);  cp_commit();

    #pragma unroll
    for (int i = 0; i < 8; i++) {
        if (i < 7) asm volatile("cp.async.wait_group 1;");
        else       asm volatile("cp.async.wait_group 0;");
        __syncthreads();
        if (i < 6) { issue((i + 2) % 3, (i + 2) * 32); cp_commit(); }

        int st = i % 3;
        uint base = sbase + (uint)(st * STH_ELEMS) * 2u;
        uint aAh = base, aAl = base + 2560u * 2u;
        uint aBh = base + 5120u * 2u, aBl = base + 9472u * 2u;

        #pragma unroll
        for (int ks = 0; ks < 32; ks += 16) {
            int arow = lane & 15;
            int kcol = ks + ((lane >> 4) << 3);
            uint ah[2][4], al[2][4];
            #pragma unroll
            for (int mi = 0; mi < 2; mi++) {
                uint off = (uint)((wm * 32 + mi * 16 + arow) * A_PITCH + kcol) * 2u;
                ldsm4(ah[mi][0], ah[mi][1], ah[mi][2], ah[mi][3], aAh + off);
                ldsm4(al[mi][0], al[mi][1], al[mi][2], al[mi][3], aAl + off);
            }
            uint bhf[2][4], blf[2][4];
            int brow = ks + (lane & 15);
            #pragma unroll
            for (int ng = 0; ng < 2; ng++) {
                int bcol = wn * 32 + ng * 16 + ((lane >> 4) << 3);
                uint off = (uint)(brow * B_PITCH + bcol) * 2u;
                ldsm4t(bhf[ng][0], bhf[ng][1], bhf[ng][2], bhf[ng][3], aBh + off);
                ldsm4t(blf[ng][0], blf[ng][1], blf[ng][2], blf[ng][3], aBl + off);
            }
            #pragma unroll
            for (int mi = 0; mi < 2; mi++)
                #pragma unroll
                for (int ng = 0; ng < 2; ng++) {
                    mma_bf16(acc[mi][ng * 2],     ah[mi], bhf[ng][0], bhf[ng][1]);
                    mma_bf16(acc[mi][ng * 2 + 1], ah[mi], bhf[ng][2], bhf[ng][3]);
                }
            #pragma unroll
            for (int mi = 0; mi < 2; mi++)
                #pragma unroll
                for (int ng = 0; ng < 2; ng++) {
                    mma_bf16(acc[mi][ng * 2],     al[mi], bhf[ng][0], bhf[ng][1]);
                    mma_bf16(acc[mi][ng * 2 + 1], al[mi], bhf[ng][2], bhf[ng][3]);
                }
            #pragma unroll
            for (int mi = 0; mi < 2; mi++)
                #pragma unroll
                for (int ng = 0; ng < 2; ng++) {
                    mma_bf16(acc[mi][ng * 2],     ah[mi], blf[ng][0], blf[ng][1]);
                    mma_bf16(acc[mi][ng * 2 + 1], ah[mi], blf[ng][2], blf[ng][3]);
                }
        }
    }

    int grp = lane >> 2, q = lane & 3;
    #pragma unroll
    for (int mi = 0; mi < 2; mi++) {
        int rb = row0 + wm * 32 + mi * 16 + grp;
        #pragma unroll
        for (int nj = 0; nj < 4; nj++) {
            int cb = col0 + wn * 32 + nj * 8 + q * 2;
            float b0 = bias[cb], b1 = bias[cb + 1];
            float v0 = fmaxf(acc[mi][nj][0] + b0, 0.f);
            float v1 = fmaxf(acc[mi][nj][1] + b1, 0.f);
            float v2 = fmaxf(acc[mi][nj][2] + b0, 0.f);
            float v3 = fmaxf(acc[mi][nj][3] + b1, 0.f);
            if (rb < NN) {
                size_t o = (size_t)rb * DD + cb;
                bf16 h0, l0, h1, l1;
                f32split(v0, h0, l0); f32split(v1, h1, l1);
                Chi[o] = h0; Chi[o + 1] = h1;
                Clo[o] = l0; Clo[o + 1] = l1;
            }
            if (rb + 8 < NN) {
                size_t o = (size_t)(rb + 8) * DD + cb;
                bf16 h2, l2, h3, l3;
                f32split(v2, h2, l2); f32split(v3, h3, l3);
                Chi[o] = h2; Chi[o + 1] = h3;
                Clo[o] = l2; Clo[o + 1] = l3;
            }
        }
    }
}

// ---------------- unified 2-product GEMM (t-mode / p-mode), 64x128 tile ---------
// stage elems: Ah@0 (64x40), Al@2560, B@5120 (32x136); total 9472
#define STG_ELEMS 9472

__global__ __launch_bounds__(256, 2) void k_gemm(
    const bf16* __restrict__ Ah, const bf16* __restrict__ Al,
    const bf16* __restrict__ Bh,
    float* __restrict__ f32_out, const float* __restrict__ bias,
    const bf16* __restrict__ rhh, const bf16* __restrict__ rhl,
    bf16* __restrict__ Chi, bf16* __restrict__ Clo)
{
    extern __shared__ __align__(16) bf16 smem[];
    int col0 = blockIdx.x * 128;
    int row0 = blockIdx.y * 64;

    int tid = threadIdx.x;
    int lane = tid & 31, warp = tid >> 5;
    int wm = warp & 1, wn = warp >> 1;

    uint sbase = (uint)__cvta_generic_to_shared(smem);
    int a_r0 = tid >> 2,        a_c0 = (tid & 3) * 8;
    int b_r0 = tid >> 4,        b_c0 = (tid & 15) * 8;
    int b_r1 = (tid + 256) >> 4;

    int ga0 = row0 + a_r0;
    uint sz0 = (ga0 < NN) ? 16u : 0u;
    int ca0 = (ga0 < NN) ? ga0 : 0;

    auto issue = [&](int st, int kt) {
        uint base = sbase + (uint)(st * STG_ELEMS) * 2u;
        uint dA0 = base + (uint)(a_r0 * A_PITCH + a_c0) * 2u;
        cp16z(dA0,            Ah + (size_t)ca0 * DD + kt + a_c0, sz0);
        cp16z(dA0 + 2560u*2u, Al + (size_t)ca0 * DD + kt + a_c0, sz0);
        uint dB0 = base + (5120u + (uint)(b_r0 * B_PITCH + b_c0)) * 2u;
        uint dB1 = base + (5120u + (uint)(b_r1 * B_PITCH + b_c0)) * 2u;
        cp16(dB0, Bh + (size_t)(kt + b_r0) * DD + col0 + b_c0);
        cp16(dB1, Bh + (size_t)(kt + b_r1) * DD + col0 + b_c0);
    };

    float acc[2][4][4] = {};
    issue(0, 0);   cp_commit();
    issue(1, 32);  cp_commit();

    #pragma unroll
    for (int i = 0; i < 8; i++) {
        if (i < 7) asm volatile("cp.async.wait_group 1;");
        else       asm volatile("cp.async.wait_group 0;");
        __syncthreads();
        if (i < 6) { issue((i + 2) % 3, (i + 2) * 32); cp_commit(); }

        int st = i % 3;
        uint base = sbase + (uint)(st * STG_ELEMS) * 2u;
        uint aAh = base, aAl = base + 2560u * 2u;
        uint aBh = base + 5120u * 2u;

        #pragma unroll
        for (int ks = 0; ks < 32; ks += 16) {
            int arow = lane & 15;
            int kcol = ks + ((lane >> 4) << 3);
            uint ah[2][4], al[2][4];
            #pragma unroll
            for (int mi = 0; mi < 2; mi++) {
                uint off = (uint)((wm * 32 + mi * 16 + arow) * A_PITCH + kcol) * 2u;
                ldsm4(ah[mi][0], ah[mi][1], ah[mi][2], ah[mi][3], aAh + off);
                ldsm4(al[mi][0], al[mi][1], al[mi][2], al[mi][3], aAl + off);
            }
            uint bhf[2][4];
            int brow = ks + (lane & 15);
            #pragma unroll
            for (int ng = 0; ng < 2; ng++) {
                int bcol = wn * 32 + ng * 16 + ((lane >> 4) << 3);
                uint off = (uint)(brow * B_PITCH + bcol) * 2u;
                ldsm4t(bhf[ng][0], bhf[ng][1], bhf[ng][2], bhf[ng][3], aBh + off);
            }
            #pragma unroll
            for (int mi = 0; mi < 2; mi++)
                #pragma unroll
                for (int ng = 0; ng < 2; ng++) {
                    mma_bf16(acc[mi][ng * 2],     ah[mi], bhf[ng][0], bhf[ng][1]);
                    mma_bf16(acc[mi][ng * 2 + 1], ah[mi], bhf[ng][2], bhf[ng][3]);
                }
            #pragma unroll
            for (int mi = 0; mi < 2; mi++)
                #pragma unroll
                for (int ng = 0; ng < 2; ng++) {
                    mma_bf16(acc[mi][ng * 2],     al[mi], bhf[ng][0], bhf[ng][1]);
                    mma_bf16(acc[mi][ng * 2 + 1], al[mi], bhf[ng][2], bhf[ng][3]);
                }
        }
    }

    int grp = lane >> 2, q = lane & 3;
    #pragma unroll
    for (int mi = 0; mi < 2; mi++) {
        int rb = row0 + wm * 32 + mi * 16 + grp;
        #pragma unroll
        for (int nj = 0; nj < 4; nj++) {
            int cb = col0 + wn * 32 + nj * 8 + q * 2;
            float v0 = acc[mi][nj][0], v1 = acc[mi][nj][1];
            float v2 = acc[mi][nj][2], v3 = acc[mi][nj][3];
            if (bias) {
                float b0 = bias[cb], b1 = bias[cb + 1];
                size_t o0 = (size_t)rb * DD + cb;
                size_t o1 = (size_t)(rb + 8) * DD + cb;
                float r00 = 0.f, r01 = 0.f, r10 = 0.f, r11 = 0.f;
                if (rb < NN) {
                    float2 a2 = __bfloat1622float2(*(const __nv_bfloat162*)(rhh + o0));
                    float2 b2 = __bfloat1622float2(*(const __nv_bfloat162*)(rhl + o0));
                    r00 = a2.x + b2.x; r01 = a2.y + b2.y;
                }
                if (rb + 8 < NN) {
                    float2 a2 = __bfloat1622float2(*(const __nv_bfloat162*)(rhh + o1));
                    float2 b2 = __bfloat1622float2(*(const __nv_bfloat162*)(rhl + o1));
                    r10 = a2.x + b2.x; r11 = a2.y + b2.y;
                }
                v0 = fmaxf(v0 + b0 + r00, 0.f);
                v1 = fmaxf(v1 + b1 + r01, 0.f);
                v2 = fmaxf(v2 + b0 + r10, 0.f);
                v3 = fmaxf(v3 + b1 + r11, 0.f);
            }
            if (rb < NN) {
                size_t o = (size_t)rb * DD + cb;
                if (f32_out) { f32_out[o] = v0; f32_out[o + 1] = v1; }
                if (Chi) {
                    bf16 h0, l0, h1, l1;
                    f32split(v0, h0, l0); f32split(v1, h1, l1);
                    Chi[o] = h0; Chi[o + 1] = h1;
                    Clo[o] = l0; Clo[o + 1] = l1;
                }
            }
            if (rb + 8 < NN) {
                size_t o = (size_t)(rb + 8) * DD + cb;
                if (f32_out) { f32_out[o] = v2; f32_out[o + 1] = v3; }
                if (Chi) {
                    bf16 h2, l2, h3, l3;
                    f32split(v2, h2, l2); f32split(v3, h3, l3);
                    Chi[o] = h2; Chi[o + 1] = h3;
                    Clo[o] = l2; Clo[o + 1] = l3;
                }
            }
        }
    }
}

// ---------------- per-node online-softmax h-aggregation -------------------------
__global__ __launch_bounds__(256) void k_edge(
    const bf16* __restrict__ hhin,
    bf16* __restrict__ agg_hi, bf16* __restrict__ agg_lo)
{
    int gw = (blockIdx.x * blockDim.x + threadIdx.x) >> 5;
    int lane = threadIdx.x & 31;
    if (gw >= NN) return;
    int n = gw;
    int c0 = lane * 8;

    float t8[8];
    *(float4*)&t8[0] = *(const float4*)(g_t + (size_t)n * DD + c0);
    *(float4*)&t8[4] = *(const float4*)(g_t + (size_t)n * DD + c0 + 4);

    float m = -INFINITY, s = 0.f;
    float acc[8] = {};

    int e0 = g_off[n], e1 = g_off[n + 1];
    uint4 hv0, hv1;
    if (e0 < e1) {
        int sN = g_srcs[e0];
        hv0 = *(const uint4*)(hhin + (size_t)sN * DD + c0);
    }
    if (e0 + 1 < e1) {
        int sN = g_srcs[e0 + 1];
        hv1 = *(const uint4*)(hhin + (size_t)sN * DD + c0);
    }
    for (int e = e0; e < e1; e++) {
        uint4 hv = hv0;
        hv0 = hv1;
        if (e + 2 < e1) {
            int sN = g_srcs[e + 2];
            hv1 = *(const uint4*)(hhin + (size_t)sN * DD + c0);
        }

        const __nv_bfloat162* hp = (const __nv_bfloat162*)&hv;
        float hf[8];
        #pragma unroll
        for (int j = 0; j < 4; j++) {
            float2 f = __bfloat1622float2(hp[j]);
            hf[2 * j] = f.x; hf[2 * j + 1] = f.y;
        }
        float d = 0.f;
        #pragma unroll
        for (int j = 0; j < 8; j++) d += t8[j] * hf[j];
        #pragma unroll
        for (int o = 16; o > 0; o >>= 1) d += __shfl_xor_sync(0xffffffffu, d, o);
        d *= 0.0625f;

        float nm = fmaxf(m, d);
        float c = __expf(m - nm);
        float w = __expf(d - nm);
        s = s * c + w;
        m = nm;

        #pragma unroll
        for (int j = 0; j < 8; j++)
            acc[j] = acc[j] * c + w * hf[j];
    }

    float inv = 1.0f / (s + 1e-9f);
    bf16 hh8[8], hl8[8];
    #pragma unroll
    for (int j = 0; j < 8; j++) f32split(acc[j] * inv, hh8[j], hl8[j]);
    *(uint4*)(agg_hi + (size_t)n * DD + c0) = *(uint4*)&hh8[0];
    *(uint4*)(agg_lo + (size_t)n * DD + c0) = *(uint4*)&hl8[0];
}

// ---------------- launch ----------------------------------------------------------
extern "C" void kernel_launch(void* const* d_in, const int* in_sizes, int n_in,
                              void* d_out, int out_size)
{
    const float* x    = (const float*)d_in[0];
    const int*   edges= (const int*)  d_in[1];
    const float* w_in = (const float*)d_in[2];
    const float* b_in = (const float*)d_in[3];
    const float* wq   = (const float*)d_in[4];
    const float* wk   = (const float*)d_in[5];
    const float* wv   = (const float*)d_in[6];
    const float* wp   = (const float*)d_in[7];
    const float* bp   = (const float*)d_in[8];
    float* out = (float*)d_out;

    const int* src = edges;
    const int* dst = edges + NE;

    float *pt;
    bf16 *pxh, *pxl, *phhA, *phlA, *phhB, *phlB, *pwinh, *pwinl, *pMh, *pWh;
    cudaGetSymbolAddress((void**)&pt,    g_t);
    cudaGetSymbolAddress((void**)&pxh,   g_xh);
    cudaGetSymbolAddress((void**)&pxl,   g_xl);
    cudaGetSymbolAddress((void**)&phhA,  g_hhA);
    cudaGetSymbolAddress((void**)&phlA,  g_hlA);
    cudaGetSymbolAddress((void**)&phhB,  g_hhB);
    cudaGetSymbolAddress((void**)&phlB,  g_hlB);
    cudaGetSymbolAddress((void**)&pwinh, g_winh);
    cudaGetSymbolAddress((void**)&pwinl, g_winl);
    cudaGetSymbolAddress((void**)&pMh,   g_Mh);
    cudaGetSymbolAddress((void**)&pWh,   g_Wh);

    static bool attr_set = false;
    if (!attr_set) {
        cudaFuncSetAttribute(k_mma_h0, cudaFuncAttributeMaxDynamicSharedMemorySize,
                             3 * STH_ELEMS * 2);
        cudaFuncSetAttribute(k_gemm, cudaFuncAttributeMaxDynamicSharedMemorySize,
                             3 * STG_ELEMS * 2);
        attr_set = true;
    }

    dim3 gw(2, 157);   // 64-row tiles: 157*64 = 10048 >= NN

    // 1: fused conversions
    k_cvt2<<<(NN * DD + DD * DD + 255) / 256, 256>>>(
        x, pxh, pxl, NN * DD, w_in, pwinh, pwinl, DD * DD);
    // 2: weight folding
    k_small<<<dim3(4, 4, 6), 256>>>(wq, wk, wv, wp, pMh, pWh);
    // 3: h0 = relu(x @ w_in + b_in)
    k_mma_h0<<<gw, 256, 3 * STH_ELEMS * 2>>>(
        pxh, pxl, pwinh, pwinl, b_in, phhA, phlA);
    // 4: layer-0 t GEMM (profiled slot)
    k_gemm<<<gw, 256, 3 * STG_ELEMS * 2>>>(
        phhA, phlA, pMh, pt, nullptr, nullptr, nullptr, nullptr, nullptr);

    // CSR build
    k_init   <<<(NN + 255) / 256, 256>>>();
    k_hist   <<<(NE + 255) / 256, 256>>>(dst);
    k_scan   <<<1, 1024>>>();
    k_scatter<<<(NE + 255) / 256, 256>>>(src, dst);

    // agg buffers reuse x hi/lo (h0 already consumed them)
    bf16* paggh = pxh;
    bf16* paggl = pxl;

    bf16* chh = phhA; bf16* chl = phlA;
    bf16* nhh = phhB; bf16* nhl = phlB;
    for (int l = 0; l < NL; l++) {
        if (l > 0)
            k_gemm<<<gw, 256, 3 * STG_ELEMS * 2>>>(
                chh, chl, pMh + l * DD * DD, pt,
                nullptr, nullptr, nullptr, nullptr, nullptr);
        // edge: aggregate h with softmax weights
        k_edge<<<(NN * 32 + 255) / 256, 256>>>(chh, paggh, paggl);
        // p GEMM: hnext = relu(agg @ wvp + bp + h)
        float* ho = (l == NL - 1) ? out : nullptr;
        bf16* oh = (l == NL - 1) ? nullptr : nhh;
        bf16* ol = (l == NL - 1) ? nullptr : nhl;
        k_gemm<<<gw, 256, 3 * STG_ELEMS * 2>>>(
            paggh, paggl, pWh + l * DD * DD, ho,
            bp + l * DD, chh, chl, oh, ol);
        bf16* t1 = chh; chh = nhh; nhh = t1;
        bf16* t2 = chl; chl = nhl; nhl = t2;
    }
}

// round 10
// speedup vs baseline: 1.2524x; 1.0873x over previous
#include <cuda_runtime.h>
#include <cuda_bf16.h>
#include <stdint.h>
#include <math.h>

#define NN 10000
#define NE 320000
#define DD 256
#define NL 3

typedef __nv_bfloat16 bf16;
typedef unsigned int uint;

// ---------------- scratch -----------------------------------------------------
__device__ float g_t[NN * DD];
__device__ bf16  g_xh[NN * DD], g_xl[NN * DD];          // x hi/lo, reused as agg hi/lo
__device__ bf16  g_hhA[NN * DD], g_hlA[NN * DD];
__device__ bf16  g_hhB[NN * DD], g_hlB[NN * DD];
__device__ bf16  g_winh[DD * DD], g_winl[DD * DD];
__device__ bf16  g_Mh[NL * DD * DD];                    // wq wk^T (bf16 hi)
__device__ bf16  g_Wh[NL * DD * DD];                    // wv wp   (bf16 hi)
__device__ int   g_deg[NN];
__device__ int   g_off[NN + 1];
__device__ int   g_cur[NN];
__device__ int   g_srcs[NE];

// ---------------- helpers -----------------------------------------------------
__device__ __forceinline__ void f32split(float v, bf16& h, bf16& l) {
    h = __float2bfloat16(v);
    l = __float2bfloat16(v - __bfloat162float(h));
}
__device__ __forceinline__ void ldsm4(uint& r0, uint& r1, uint& r2, uint& r3, uint addr) {
    asm volatile("ldmatrix.sync.aligned.m8n8.x4.shared.b16 {%0,%1,%2,%3}, [%4];"
                 : "=r"(r0), "=r"(r1), "=r"(r2), "=r"(r3) : "r"(addr));
}
__device__ __forceinline__ void ldsm4t(uint& r0, uint& r1, uint& r2, uint& r3, uint addr) {
    asm volatile("ldmatrix.sync.aligned.m8n8.x4.trans.shared.b16 {%0,%1,%2,%3}, [%4];"
                 : "=r"(r0), "=r"(r1), "=r"(r2), "=r"(r3) : "r"(addr));
}
__device__ __forceinline__ void mma_bf16(float* c, const uint* a, uint b0, uint b1) {
    asm volatile("mma.sync.aligned.m16n8k16.row.col.f32.bf16.bf16.f32 "
                 "{%0,%1,%2,%3},{%4,%5,%6,%7},{%8,%9},{%0,%1,%2,%3};"
                 : "+f"(c[0]), "+f"(c[1]), "+f"(c[2]), "+f"(c[3])
                 : "r"(a[0]), "r"(a[1]), "r"(a[2]), "r"(a[3]), "r"(b0), "r"(b1));
}
__device__ __forceinline__ void cp16(uint dst, const void* src) {
    asm volatile("cp.async.cg.shared.global [%0], [%1], 16;" :: "r"(dst), "l"(src));
}
__device__ __forceinline__ void cp16z(uint dst, const void* src, uint sz) {
    asm volatile("cp.async.cg.shared.global [%0], [%1], 16, %2;" :: "r"(dst), "l"(src), "r"(sz));
}
__device__ __forceinline__ void cp_commit() { asm volatile("cp.async.commit_group;"); }

// ---------------- CSR build ----------------------------------------------------
__global__ void k_init() {
    int i = blockIdx.x * blockDim.x + threadIdx.x;
    if (i < NN) { g_deg[i] = 0; g_cur[i] = 0; }
}
__global__ void k_hist(const int* __restrict__ dst) {
    int e = blockIdx.x * blockDim.x + threadIdx.x;
    if (e < NE) atomicAdd(&g_deg[dst[e]], 1);
}
__global__ void k_scan() {
    __shared__ int ws[32];
    int tid = threadIdx.x, lane = tid & 31, wid = tid >> 5;
    int carry = 0;
    for (int base = 0; base < NN; base += 1024) {
        int x = (base + tid < NN) ? g_deg[base + tid] : 0;
        int v = x;
        #pragma unroll
        for (int o = 1; o < 32; o <<= 1) {
            int y = __shfl_up_sync(0xffffffffu, v, o);
            if (lane >= o) v += y;
        }
        if (lane == 31) ws[wid] = v;
        __syncthreads();
        if (tid < 32) {
            int w = ws[tid];
            #pragma unroll
            for (int o = 1; o < 32; o <<= 1) {
                int y = __shfl_up_sync(0xffffffffu, w, o);
                if (tid >= o) w += y;
            }
            ws[tid] = w;
        }
        __syncthreads();
        int add = wid ? ws[wid - 1] : 0;
        if (base + tid < NN) g_off[base + tid] = carry + add + v - x;
        int tot = ws[31];
        __syncthreads();
        carry += tot;
    }
    if (tid == 0) g_off[NN] = carry;
}
__global__ void k_scatter(const int* __restrict__ src, const int* __restrict__ dst) {
    int e = blockIdx.x * blockDim.x + threadIdx.x;
    if (e < NE) {
        int d = dst[e];
        int pos = g_off[d] + atomicAdd(&g_cur[d], 1);
        g_srcs[pos] = src[e];
    }
}

// ---------------- fused fp32 -> bf16 hi/lo (x and w_in) -------------------------
__global__ void k_cvt2(const float* __restrict__ a, bf16* __restrict__ ah,
                       bf16* __restrict__ al, int na,
                       const float* __restrict__ b, bf16* __restrict__ bh,
                       bf16* __restrict__ bl, int nb) {
    int i = blockIdx.x * blockDim.x + threadIdx.x;
    if (i < na) {
        bf16 h, l; f32split(a[i], h, l); ah[i] = h; al[i] = l;
    } else if (i < na + nb) {
        int j = i - na;
        bf16 h, l; f32split(b[j], h, l); bh[j] = h; bl[j] = l;
    }
}

// ---------------- weight folding (bf16-hi outputs) -------------------------------
__global__ __launch_bounds__(256) void k_small(
    const float* __restrict__ wq, const float* __restrict__ wk,
    const float* __restrict__ wv, const float* __restrict__ wp,
    bf16* __restrict__ pMh, bf16* __restrict__ pWh)
{
    int z = blockIdx.z;
    const float* A; const float* B; bf16* Ch; int tb;
    if (z < 3) { A = wq + z * DD * DD; B = wk + z * DD * DD;
                 Ch = pMh + z * DD * DD; tb = 1; }
    else       { A = wv + (z - 3) * DD * DD; B = wp + (z - 3) * DD * DD;
                 Ch = pWh + (z - 3) * DD * DD; tb = 0; }

    __shared__ float As[16][65];
    __shared__ float Bs[16][65];
    int tid = threadIdx.x;
    int tx = tid & 15, ty = tid >> 4;
    int row0 = blockIdx.y * 64, col0 = blockIdx.x * 64;
    float acc[4][4] = {};

    for (int kt = 0; kt < DD; kt += 16) {
        {
            int r = tid >> 2, c = (tid & 3) * 4;
            float4 v = *(const float4*)(A + (row0 + r) * DD + kt + c);
            As[c + 0][r] = v.x; As[c + 1][r] = v.y; As[c + 2][r] = v.z; As[c + 3][r] = v.w;
        }
        if (tb) {
            int c = tid >> 2, k = (tid & 3) * 4;
            float4 v = *(const float4*)(B + (col0 + c) * DD + kt + k);
            Bs[k + 0][c] = v.x; Bs[k + 1][c] = v.y; Bs[k + 2][c] = v.z; Bs[k + 3][c] = v.w;
        } else {
            int k = tid >> 4, c = (tid & 15) * 4;
            float4 v = *(const float4*)(B + (kt + k) * DD + col0 + c);
            Bs[k][c + 0] = v.x; Bs[k][c + 1] = v.y; Bs[k][c + 2] = v.z; Bs[k][c + 3] = v.w;
        }
        __syncthreads();
        #pragma unroll
        for (int kk = 0; kk < 16; kk++) {
            float a[4], b[4];
            #pragma unroll
            for (int i = 0; i < 4; i++) { a[i] = As[kk][ty * 4 + i]; b[i] = Bs[kk][tx * 4 + i]; }
            #pragma unroll
            for (int i = 0; i < 4; i++)
                #pragma unroll
                for (int j = 0; j < 4; j++)
                    acc[i][j] += a[i] * b[j];
        }
        __syncthreads();
    }
    #pragma unroll
    for (int i = 0; i < 4; i++)
        #pragma unroll
        for (int j = 0; j < 4; j++)
            Ch[(row0 + ty * 4 + i) * DD + col0 + tx * 4 + j] = __float2bfloat16(acc[i][j]);
}

// ---------------- h0 GEMM: 64x128 tile, 3 products, occ 2 -----------------------
#define STH_ELEMS 13824
#define A_PITCH 40
#define B_PITCH 136

__global__ __launch_bounds__(256, 2) void k_mma_h0(
    const bf16* __restrict__ Ah, const bf16* __restrict__ Al,
    const bf16* __restrict__ Bh, const bf16* __restrict__ Bl,
    const float* __restrict__ bias,
    bf16* __restrict__ Chi, bf16* __restrict__ Clo)
{
    extern __shared__ __align__(16) bf16 smem[];
    int tid = threadIdx.x;
    int lane = tid & 31, warp = tid >> 5;
    int wm = warp & 1, wn = warp >> 1;
    int row0 = blockIdx.y * 64, col0 = blockIdx.x * 128;

    uint sbase = (uint)__cvta_generic_to_shared(smem);
    int a_r0 = tid >> 2,        a_c0 = (tid & 3) * 8;
    int b_r0 = tid >> 4,        b_c0 = (tid & 15) * 8;
    int b_r1 = (tid + 256) >> 4;

    int ga0 = row0 + a_r0;
    uint sz0 = (ga0 < NN) ? 16u : 0u;
    int ca0 = (ga0 < NN) ? ga0 : 0;

    auto issue = [&](int st, int kt) {
        uint base = sbase + (uint)(st * STH_ELEMS) * 2u;
        uint dA0 = base + (uint)(a_r0 * A_PITCH + a_c0) * 2u;
        cp16z(dA0,            Ah + (size_t)ca0 * DD + kt + a_c0, sz0);
        cp16z(dA0 + 2560u*2u, Al + (size_t)ca0 * DD + kt + a_c0, sz0);
        uint dB0 = base + (5120u + (uint)(b_r0 * B_PITCH + b_c0)) * 2u;
        uint dB1 = base + (5120u + (uint)(b_r1 * B_PITCH + b_c0)) * 2u;
        cp16(dB0, Bh + (size_t)(kt + b_r0) * DD + col0 + b_c0);
        cp16(dB1, Bh + (size_t)(kt + b_r1) * DD + col0 + b_c0);
        cp16(dB0 + 4352u*2u, Bl + (size_t)(kt + b_r0) * DD + col0 + b_c0);
        cp16(dB1 + 4352u*2u, Bl + (size_t)(kt + b_r1) * DD + col0 + b_c0);
    };

    float acc[2][4][4] = {};
    issue(0, 0);   cp_commit();
    issue(1, 32);  cp_commit();

    #pragma unroll
    for (int i = 0; i < 8; i++) {
        if (i < 7) asm volatile("cp.async.wait_group 1;");
        else       asm volatile("cp.async.wait_group 0;");
        __syncthreads();
        if (i < 6) { issue((i + 2) % 3, (i + 2) * 32); cp_commit(); }

        int st = i % 3;
        uint base = sbase + (uint)(st * STH_ELEMS) * 2u;
        uint aAh = base, aAl = base + 2560u * 2u;
        uint aBh = base + 5120u * 2u, aBl = base + 9472u * 2u;

        #pragma unroll
        for (int ks = 0; ks < 32; ks += 16) {
            int arow = lane & 15;
            int kcol = ks + ((lane >> 4) << 3);
            uint ah[2][4], al[2][4];
            #pragma unroll
            for (int mi = 0; mi < 2; mi++) {
                uint off = (uint)((wm * 32 + mi * 16 + arow) * A_PITCH + kcol) * 2u;
                ldsm4(ah[mi][0], ah[mi][1], ah[mi][2], ah[mi][3], aAh + off);
                ldsm4(al[mi][0], al[mi][1], al[mi][2], al[mi][3], aAl + off);
            }
            uint bhf[2][4], blf[2][4];
            int brow = ks + (lane & 15);
            #pragma unroll
            for (int ng = 0; ng < 2; ng++) {
                int bcol = wn * 32 + ng * 16 + ((lane >> 4) << 3);
                uint off = (uint)(brow * B_PITCH + bcol) * 2u;
                ldsm4t(bhf[ng][0], bhf[ng][1], bhf[ng][2], bhf[ng][3], aBh + off);
                ldsm4t(blf[ng][0], blf[ng][1], blf[ng][2], blf[ng][3], aBl + off);
            }
            #pragma unroll
            for (int mi = 0; mi < 2; mi++)
                #pragma unroll
                for (int ng = 0; ng < 2; ng++) {
                    mma_bf16(acc[mi][ng * 2],     ah[mi], bhf[ng][0], bhf[ng][1]);
                    mma_bf16(acc[mi][ng * 2 + 1], ah[mi], bhf[ng][2], bhf[ng][3]);
                }
            #pragma unroll
            for (int mi = 0; mi < 2; mi++)
                #pragma unroll
                for (int ng = 0; ng < 2; ng++) {
                    mma_bf16(acc[mi][ng * 2],     al[mi], bhf[ng][0], bhf[ng][1]);
                    mma_bf16(acc[mi][ng * 2 + 1], al[mi], bhf[ng][2], bhf[ng][3]);
                }
            #pragma unroll
            for (int mi = 0; mi < 2; mi++)
                #pragma unroll
                for (int ng = 0; ng < 2; ng++) {
                    mma_bf16(acc[mi][ng * 2],     ah[mi], blf[ng][0], blf[ng][1]);
                    mma_bf16(acc[mi][ng * 2 + 1], ah[mi], blf[ng][2], blf[ng][3]);
                }
        }
    }

    int grp = lane >> 2, q = lane & 3;
    #pragma unroll
    for (int mi = 0; mi < 2; mi++) {
        int rb = row0 + wm * 32 + mi * 16 + grp;
        #pragma unroll
        for (int nj = 0; nj < 4; nj++) {
            int cb = col0 + wn * 32 + nj * 8 + q * 2;
            float b0 = bias[cb], b1 = bias[cb + 1];
            float v0 = fmaxf(acc[mi][nj][0] + b0, 0.f);
            float v1 = fmaxf(acc[mi][nj][1] + b1, 0.f);
            float v2 = fmaxf(acc[mi][nj][2] + b0, 0.f);
            float v3 = fmaxf(acc[mi][nj][3] + b1, 0.f);
            if (rb < NN) {
                size_t o = (size_t)rb * DD + cb;
                bf16 h0, l0, h1, l1;
                f32split(v0, h0, l0); f32split(v1, h1, l1);
                Chi[o] = h0; Chi[o + 1] = h1;
                Clo[o] = l0; Clo[o + 1] = l1;
            }
            if (rb + 8 < NN) {
                size_t o = (size_t)(rb + 8) * DD + cb;
                bf16 h2, l2, h3, l3;
                f32split(v2, h2, l2); f32split(v3, h3, l3);
                Chi[o] = h2; Chi[o + 1] = h3;
                Clo[o] = l2; Clo[o + 1] = l3;
            }
        }
    }
}

// ---------------- unified 2-product GEMM (t-mode / p-mode), 64x128 tile ---------
#define STG_ELEMS 9472

__global__ __launch_bounds__(256, 2) void k_gemm(
    const bf16* __restrict__ Ah, const bf16* __restrict__ Al,
    const bf16* __restrict__ Bh,
    float* __restrict__ f32_out, const float* __restrict__ bias,
    const bf16* __restrict__ rhh, const bf16* __restrict__ rhl,
    bf16* __restrict__ Chi, bf16* __restrict__ Clo)
{
    extern __shared__ __align__(16) bf16 smem[];
    int col0 = blockIdx.x * 128;
    int row0 = blockIdx.y * 64;

    int tid = threadIdx.x;
    int lane = tid & 31, warp = tid >> 5;
    int wm = warp & 1, wn = warp >> 1;

    uint sbase = (uint)__cvta_generic_to_shared(smem);
    int a_r0 = tid >> 2,        a_c0 = (tid & 3) * 8;
    int b_r0 = tid >> 4,        b_c0 = (tid & 15) * 8;
    int b_r1 = (tid + 256) >> 4;

    int ga0 = row0 + a_r0;
    uint sz0 = (ga0 < NN) ? 16u : 0u;
    int ca0 = (ga0 < NN) ? ga0 : 0;

    auto issue = [&](int st, int kt) {
        uint base = sbase + (uint)(st * STG_ELEMS) * 2u;
        uint dA0 = base + (uint)(a_r0 * A_PITCH + a_c0) * 2u;
        cp16z(dA0,            Ah + (size_t)ca0 * DD + kt + a_c0, sz0);
        cp16z(dA0 + 2560u*2u, Al + (size_t)ca0 * DD + kt + a_c0, sz0);
        uint dB0 = base + (5120u + (uint)(b_r0 * B_PITCH + b_c0)) * 2u;
        uint dB1 = base + (5120u + (uint)(b_r1 * B_PITCH + b_c0)) * 2u;
        cp16(dB0, Bh + (size_t)(kt + b_r0) * DD + col0 + b_c0);
        cp16(dB1, Bh + (size_t)(kt + b_r1) * DD + col0 + b_c0);
    };

    float acc[2][4][4] = {};
    issue(0, 0);   cp_commit();
    issue(1, 32);  cp_commit();

    #pragma unroll
    for (int i = 0; i < 8; i++) {
        if (i < 7) asm volatile("cp.async.wait_group 1;");
        else       asm volatile("cp.async.wait_group 0;");
        __syncthreads();
        if (i < 6) { issue((i + 2) % 3, (i + 2) * 32); cp_commit(); }

        int st = i % 3;
        uint base = sbase + (uint)(st * STG_ELEMS) * 2u;
        uint aAh = base, aAl = base + 2560u * 2u;
        uint aBh = base + 5120u * 2u;

        #pragma unroll
        for (int ks = 0; ks < 32; ks += 16) {
            int arow = lane & 15;
            int kcol = ks + ((lane >> 4) << 3);
            uint ah[2][4], al[2][4];
            #pragma unroll
            for (int mi = 0; mi < 2; mi++) {
                uint off = (uint)((wm * 32 + mi * 16 + arow) * A_PITCH + kcol) * 2u;
                ldsm4(ah[mi][0], ah[mi][1], ah[mi][2], ah[mi][3], aAh + off);
                ldsm4(al[mi][0], al[mi][1], al[mi][2], al[mi][3], aAl + off);
            }
            uint bhf[2][4];
            int brow = ks + (lane & 15);
            #pragma unroll
            for (int ng = 0; ng < 2; ng++) {
                int bcol = wn * 32 + ng * 16 + ((lane >> 4) << 3);
                uint off = (uint)(brow * B_PITCH + bcol) * 2u;
                ldsm4t(bhf[ng][0], bhf[ng][1], bhf[ng][2], bhf[ng][3], aBh + off);
            }
            #pragma unroll
            for (int mi = 0; mi < 2; mi++)
                #pragma unroll
                for (int ng = 0; ng < 2; ng++) {
                    mma_bf16(acc[mi][ng * 2],     ah[mi], bhf[ng][0], bhf[ng][1]);
                    mma_bf16(acc[mi][ng * 2 + 1], ah[mi], bhf[ng][2], bhf[ng][3]);
                }
            #pragma unroll
            for (int mi = 0; mi < 2; mi++)
                #pragma unroll
                for (int ng = 0; ng < 2; ng++) {
                    mma_bf16(acc[mi][ng * 2],     al[mi], bhf[ng][0], bhf[ng][1]);
                    mma_bf16(acc[mi][ng * 2 + 1], al[mi], bhf[ng][2], bhf[ng][3]);
                }
        }
    }

    int grp = lane >> 2, q = lane & 3;
    #pragma unroll
    for (int mi = 0; mi < 2; mi++) {
        int rb = row0 + wm * 32 + mi * 16 + grp;
        #pragma unroll
        for (int nj = 0; nj < 4; nj++) {
            int cb = col0 + wn * 32 + nj * 8 + q * 2;
            float v0 = acc[mi][nj][0], v1 = acc[mi][nj][1];
            float v2 = acc[mi][nj][2], v3 = acc[mi][nj][3];
            if (bias) {
                float b0 = bias[cb], b1 = bias[cb + 1];
                size_t o0 = (size_t)rb * DD + cb;
                size_t o1 = (size_t)(rb + 8) * DD + cb;
                float r00 = 0.f, r01 = 0.f, r10 = 0.f, r11 = 0.f;
                if (rb < NN) {
                    float2 a2 = __bfloat1622float2(*(const __nv_bfloat162*)(rhh + o0));
                    float2 b2 = __bfloat1622float2(*(const __nv_bfloat162*)(rhl + o0));
                    r00 = a2.x + b2.x; r01 = a2.y + b2.y;
                }
                if (rb + 8 < NN) {
                    float2 a2 = __bfloat1622float2(*(const __nv_bfloat162*)(rhh + o1));
                    float2 b2 = __bfloat1622float2(*(const __nv_bfloat162*)(rhl + o1));
                    r10 = a2.x + b2.x; r11 = a2.y + b2.y;
                }
                v0 = fmaxf(v0 + b0 + r00, 0.f);
                v1 = fmaxf(v1 + b1 + r01, 0.f);
                v2 = fmaxf(v2 + b0 + r10, 0.f);
                v3 = fmaxf(v3 + b1 + r11, 0.f);
            }
            if (rb < NN) {
                size_t o = (size_t)rb * DD + cb;
                if (f32_out) { f32_out[o] = v0; f32_out[o + 1] = v1; }
                if (Chi) {
                    bf16 h0, l0, h1, l1;
                    f32split(v0, h0, l0); f32split(v1, h1, l1);
                    Chi[o] = h0; Chi[o + 1] = h1;
                    Clo[o] = l0; Clo[o + 1] = l1;
                }
            }
            if (rb + 8 < NN) {
                size_t o = (size_t)(rb + 8) * DD + cb;
                if (f32_out) { f32_out[o] = v2; f32_out[o + 1] = v3; }
                if (Chi) {
                    bf16 h2, l2, h3, l3;
                    f32split(v2, h2, l2); f32split(v3, h3, l3);
                    Chi[o] = h2; Chi[o + 1] = h3;
                    Clo[o] = l2; Clo[o + 1] = l3;
                }
            }
        }
    }
}

// ---------------- per-node online-softmax h-aggregation -------------------------
__global__ __launch_bounds__(256) void k_edge(
    const bf16* __restrict__ hhin,
    bf16* __restrict__ agg_hi, bf16* __restrict__ agg_lo)
{
    int gw = (blockIdx.x * blockDim.x + threadIdx.x) >> 5;
    int lane = threadIdx.x & 31;
    if (gw >= NN) return;
    int n = gw;
    int c0 = lane * 8;

    float t8[8];
    *(float4*)&t8[0] = *(const float4*)(g_t + (size_t)n * DD + c0);
    *(float4*)&t8[4] = *(const float4*)(g_t + (size_t)n * DD + c0 + 4);

    float m = -INFINITY, s = 0.f;
    float acc[8] = {};

    int e0 = g_off[n], e1 = g_off[n + 1];
    uint4 hv0, hv1;
    if (e0 < e1) {
        int sN = g_srcs[e0];
        hv0 = *(const uint4*)(hhin + (size_t)sN * DD + c0);
    }
    if (e0 + 1 < e1) {
        int sN = g_srcs[e0 + 1];
        hv1 = *(const uint4*)(hhin + (size_t)sN * DD + c0);
    }
    for (int e = e0; e < e1; e++) {
        uint4 hv = hv0;
        hv0 = hv1;
        if (e + 2 < e1) {
            int sN = g_srcs[e + 2];
            hv1 = *(const uint4*)(hhin + (size_t)sN * DD + c0);
        }

        const __nv_bfloat162* hp = (const __nv_bfloat162*)&hv;
        float hf[8];
        #pragma unroll
        for (int j = 0; j < 4; j++) {
            float2 f = __bfloat1622float2(hp[j]);
            hf[2 * j] = f.x; hf[2 * j + 1] = f.y;
        }
        float d = 0.f;
        #pragma unroll
        for (int j = 0; j < 8; j++) d += t8[j] * hf[j];
        #pragma unroll
        for (int o = 16; o > 0; o >>= 1) d += __shfl_xor_sync(0xffffffffu, d, o);
        d *= 0.0625f;

        float nm = fmaxf(m, d);
        float c = __expf(m - nm);
        float w = __expf(d - nm);
        s = s * c + w;
        m = nm;

        #pragma unroll
        for (int j = 0; j < 8; j++)
            acc[j] = acc[j] * c + w * hf[j];
    }

    float inv = 1.0f / (s + 1e-9f);
    bf16 hh8[8], hl8[8];
    #pragma unroll
    for (int j = 0; j < 8; j++) f32split(acc[j] * inv, hh8[j], hl8[j]);
    *(uint4*)(agg_hi + (size_t)n * DD + c0) = *(uint4*)&hh8[0];
    *(uint4*)(agg_lo + (size_t)n * DD + c0) = *(uint4*)&hl8[0];
}

// ---------------- launch ----------------------------------------------------------
extern "C" void kernel_launch(void* const* d_in, const int* in_sizes, int n_in,
                              void* d_out, int out_size)
{
    const float* x    = (const float*)d_in[0];
    const int*   edges= (const int*)  d_in[1];
    const float* w_in = (const float*)d_in[2];
    const float* b_in = (const float*)d_in[3];
    const float* wq   = (const float*)d_in[4];
    const float* wk   = (const float*)d_in[5];
    const float* wv   = (const float*)d_in[6];
    const float* wp   = (const float*)d_in[7];
    const float* bp   = (const float*)d_in[8];
    float* out = (float*)d_out;

    const int* src = edges;
    const int* dst = edges + NE;

    float *pt;
    bf16 *pxh, *pxl, *phhA, *phlA, *phhB, *phlB, *pwinh, *pwinl, *pMh, *pWh;
    cudaGetSymbolAddress((void**)&pt,    g_t);
    cudaGetSymbolAddress((void**)&pxh,   g_xh);
    cudaGetSymbolAddress((void**)&pxl,   g_xl);
    cudaGetSymbolAddress((void**)&phhA,  g_hhA);
    cudaGetSymbolAddress((void**)&phlA,  g_hlA);
    cudaGetSymbolAddress((void**)&phhB,  g_hhB);
    cudaGetSymbolAddress((void**)&phlB,  g_hlB);
    cudaGetSymbolAddress((void**)&pwinh, g_winh);
    cudaGetSymbolAddress((void**)&pwinl, g_winl);
    cudaGetSymbolAddress((void**)&pMh,   g_Mh);
    cudaGetSymbolAddress((void**)&pWh,   g_Wh);

    static cudaStream_t s_side = nullptr;
    static cudaEvent_t s_ev0 = nullptr, s_ev1 = nullptr;
    if (!s_side) {
        cudaFuncSetAttribute(k_mma_h0, cudaFuncAttributeMaxDynamicSharedMemorySize,
                             3 * STH_ELEMS * 2);
        cudaFuncSetAttribute(k_gemm, cudaFuncAttributeMaxDynamicSharedMemorySize,
                             3 * STG_ELEMS * 2);
        cudaStreamCreateWithFlags(&s_side, cudaStreamNonBlocking);
        cudaEventCreateWithFlags(&s_ev0, cudaEventDisableTiming);
        cudaEventCreateWithFlags(&s_ev1, cudaEventDisableTiming);
    }

    dim3 gw(2, 157);   // 64-row tiles: 157*64 = 10048 >= NN

    // ---- fork: weight folding + CSR build on side stream (independent of h0 path)
    cudaEventRecord(s_ev0, 0);
    cudaStreamWaitEvent(s_side, s_ev0, 0);
    k_small  <<<dim3(4, 4, 6), 256, 0, s_side>>>(wq, wk, wv, wp, pMh, pWh);
    k_init   <<<(NN + 255) / 256, 256, 0, s_side>>>();
    k_hist   <<<(NE + 255) / 256, 256, 0, s_side>>>(dst);
    k_scan   <<<1, 1024, 0, s_side>>>();
    k_scatter<<<(NE + 255) / 256, 256, 0, s_side>>>(src, dst);
    cudaEventRecord(s_ev1, s_side);

    // ---- main stream: conversions + h0 GEMM
    k_cvt2<<<(NN * DD + DD * DD + 255) / 256, 256>>>(
        x, pxh, pxl, NN * DD, w_in, pwinh, pwinl, DD * DD);
    k_mma_h0<<<gw, 256, 3 * STH_ELEMS * 2>>>(
        pxh, pxl, pwinh, pwinl, b_in, phhA, phlA);

    // join: t-GEMM needs pMh; edge needs CSR
    cudaStreamWaitEvent(0, s_ev1, 0);

    // agg buffers reuse x hi/lo (h0 already consumed them)
    bf16* paggh = pxh;
    bf16* paggl = pxl;

    bf16* chh = phhA; bf16* chl = phlA;
    bf16* nhh = phhB; bf16* nhl = phlB;
    for (int l = 0; l < NL; l++) {
        k_gemm<<<gw, 256, 3 * STG_ELEMS * 2>>>(
            chh, chl, pMh + l * DD * DD, pt,
            nullptr, nullptr, nullptr, nullptr, nullptr);
        // edge: aggregate h with softmax weights
        k_edge<<<(NN * 32 + 255) / 256, 256>>>(chh, paggh, paggl);
        // p GEMM: hnext = relu(agg @ wvp + bp + h)
        float* ho = (l == NL - 1) ? out : nullptr;
        bf16* oh = (l == NL - 1) ? nullptr : nhh;
        bf16* ol = (l == NL - 1) ? nullptr : nhl;
        k_gemm<<<gw, 256, 3 * STG_ELEMS * 2>>>(
            paggh, paggl, pWh + l * DD * DD, ho,
            bp + l * DD, chh, chl, oh, ol);
        bf16* t1 = chh; chh = nhh; nhh = t1;
        bf16* t2 = chl; chl = nhl; nhl = t2;
    }
}

// round 11
// speedup vs baseline: 1.2674x; 1.0119x over previous
#include <cuda_runtime.h>
#include <cuda_bf16.h>
#include <stdint.h>
#include <math.h>

#define NN 10000
#define NE 320000
#define DD 256
#define NL 3

typedef __nv_bfloat16 bf16;
typedef unsigned int uint;

// ---------------- scratch -----------------------------------------------------
__device__ float g_t[NN * DD];
__device__ bf16  g_xh[NN * DD], g_xl[NN * DD];          // x hi/lo, reused as agg hi/lo
__device__ bf16  g_hhA[NN * DD], g_hlA[NN * DD];
__device__ bf16  g_hhB[NN * DD], g_hlB[NN * DD];
__device__ bf16  g_winh[DD * DD], g_winl[DD * DD];
__device__ bf16  g_Mh[NL * DD * DD];                    // wq wk^T (bf16 hi)
__device__ bf16  g_Wh[NL * DD * DD];                    // wv wp   (bf16 hi)
__device__ int   g_deg[NN];
__device__ int   g_off[NN + 1];
__device__ int   g_cur[NN];
__device__ int   g_bt[40];
__device__ int   g_srcs[NE];

// ---------------- helpers -----------------------------------------------------
__device__ __forceinline__ void f32split(float v, bf16& h, bf16& l) {
    h = __float2bfloat16(v);
    l = __float2bfloat16(v - __bfloat162float(h));
}
__device__ __forceinline__ void ldsm4(uint& r0, uint& r1, uint& r2, uint& r3, uint addr) {
    asm volatile("ldmatrix.sync.aligned.m8n8.x4.shared.b16 {%0,%1,%2,%3}, [%4];"
                 : "=r"(r0), "=r"(r1), "=r"(r2), "=r"(r3) : "r"(addr));
}
__device__ __forceinline__ void ldsm4t(uint& r0, uint& r1, uint& r2, uint& r3, uint addr) {
    asm volatile("ldmatrix.sync.aligned.m8n8.x4.trans.shared.b16 {%0,%1,%2,%3}, [%4];"
                 : "=r"(r0), "=r"(r1), "=r"(r2), "=r"(r3) : "r"(addr));
}
__device__ __forceinline__ void mma_bf16(float* c, const uint* a, uint b0, uint b1) {
    asm volatile("mma.sync.aligned.m16n8k16.row.col.f32.bf16.bf16.f32 "
                 "{%0,%1,%2,%3},{%4,%5,%6,%7},{%8,%9},{%0,%1,%2,%3};"
                 : "+f"(c[0]), "+f"(c[1]), "+f"(c[2]), "+f"(c[3])
                 : "r"(a[0]), "r"(a[1]), "r"(a[2]), "r"(a[3]), "r"(b0), "r"(b1));
}
__device__ __forceinline__ void cp16(uint dst, const void* src) {
    asm volatile("cp.async.cg.shared.global [%0], [%1], 16;" :: "r"(dst), "l"(src));
}
__device__ __forceinline__ void cp16z(uint dst, const void* src, uint sz) {
    asm volatile("cp.async.cg.shared.global [%0], [%1], 16, %2;" :: "r"(dst), "l"(src), "r"(sz));
}
__device__ __forceinline__ void cp_commit() { asm volatile("cp.async.commit_group;"); }

// ---------------- CSR build ----------------------------------------------------
__global__ void k_init() {
    int i = blockIdx.x * blockDim.x + threadIdx.x;
    if (i < NN) { g_deg[i] = 0; g_cur[i] = 0; }
}
__global__ void k_hist(const int* __restrict__ dst) {
    int e = blockIdx.x * blockDim.x + threadIdx.x;
    if (e < NE) atomicAdd(&g_deg[dst[e]], 1);
}
// phase 1: 40 blocks x 256 — block-local exclusive scan + block totals
__global__ __launch_bounds__(256) void k_scan_part() {
    __shared__ int ws[8];
    int b = blockIdx.x, tid = threadIdx.x;
    int lane = tid & 31, wid = tid >> 5;
    int i = b * 256 + tid;
    int x = (i < NN) ? g_deg[i] : 0;
    int v = x;
    #pragma unroll
    for (int o = 1; o < 32; o <<= 1) {
        int y = __shfl_up_sync(0xffffffffu, v, o);
        if (lane >= o) v += y;
    }
    if (lane == 31) ws[wid] = v;
    __syncthreads();
    if (tid < 8) {
        int w = ws[tid];
        #pragma unroll
        for (int o = 1; o < 8; o <<= 1) {
            int y = __shfl_up_sync(0xffu, w, o);
            if (tid >= o) w += y;
        }
        ws[tid] = w;
    }
    __syncthreads();
    int add = wid ? ws[wid - 1] : 0;
    if (i < NN) g_off[i] = add + v - x;     // block-local exclusive
    if (tid == 255) g_bt[b] = add + v;      // block total
}
// phase 2: 1 warp scans 40 block totals (exclusive); also sets g_off[NN]
__global__ void k_scan_top() {
    int tid = threadIdx.x;
    int v = (tid < 40) ? g_bt[tid] : 0;
    int e = v;
    #pragma unroll
    for (int o = 1; o < 64; o <<= 1) {
        int y = __shfl_up_sync(0xffffffffu, e, o) ;
        if ((threadIdx.x & 31) >= o) e += y;
    }
    // two warps: handle 40 entries in warp 0 + warp 1 with carry
    __shared__ int carry;
    if (tid == 31) carry = e;
    __syncthreads();
    if (tid < 40) {
        int ex = e - v + ((tid >= 32) ? carry : 0);
        g_bt[tid] = ex;
    }
    if (tid == 0) g_off[NN] = NE;
}
// phase 3: add block prefixes
__global__ __launch_bounds__(256) void k_scan_add() {
    int b = blockIdx.x;
    int i = b * 256 + threadIdx.x;
    if (b > 0 && i < NN) g_off[i] += g_bt[b];
}
__global__ void k_scatter(const int* __restrict__ src, const int* __restrict__ dst) {
    int e = blockIdx.x * blockDim.x + threadIdx.x;
    if (e < NE) {
        int d = dst[e];
        int pos = g_off[d] + atomicAdd(&g_cur[d], 1);
        g_srcs[pos] = src[e];
    }
}

// ---------------- fused fp32 -> bf16 hi/lo (x and w_in) -------------------------
__global__ void k_cvt2(const float* __restrict__ a, bf16* __restrict__ ah,
                       bf16* __restrict__ al, int na,
                       const float* __restrict__ b, bf16* __restrict__ bh,
                       bf16* __restrict__ bl, int nb) {
    int i = blockIdx.x * blockDim.x + threadIdx.x;
    if (i < na) {
        bf16 h, l; f32split(a[i], h, l); ah[i] = h; al[i] = l;
    } else if (i < na + nb) {
        int j = i - na;
        bf16 h, l; f32split(b[j], h, l); bh[j] = h; bl[j] = l;
    }
}

// ---------------- weight folding (bf16-hi outputs) -------------------------------
__global__ __launch_bounds__(256) void k_small(
    const float* __restrict__ wq, const float* __restrict__ wk,
    const float* __restrict__ wv, const float* __restrict__ wp,
    bf16* __restrict__ pMh, bf16* __restrict__ pWh)
{
    int z = blockIdx.z;
    const float* A; const float* B; bf16* Ch; int tb;
    if (z < 3) { A = wq + z * DD * DD; B = wk + z * DD * DD;
                 Ch = pMh + z * DD * DD; tb = 1; }
    else       { A = wv + (z - 3) * DD * DD; B = wp + (z - 3) * DD * DD;
                 Ch = pWh + (z - 3) * DD * DD; tb = 0; }

    __shared__ float As[16][65];
    __shared__ float Bs[16][65];
    int tid = threadIdx.x;
    int tx = tid & 15, ty = tid >> 4;
    int row0 = blockIdx.y * 64, col0 = blockIdx.x * 64;
    float acc[4][4] = {};

    for (int kt = 0; kt < DD; kt += 16) {
        {
            int r = tid >> 2, c = (tid & 3) * 4;
            float4 v = *(const float4*)(A + (row0 + r) * DD + kt + c);
            As[c + 0][r] = v.x; As[c + 1][r] = v.y; As[c + 2][r] = v.z; As[c + 3][r] = v.w;
        }
        if (tb) {
            int c = tid >> 2, k = (tid & 3) * 4;
            float4 v = *(const float4*)(B + (col0 + c) * DD + kt + k);
            Bs[k + 0][c] = v.x; Bs[k + 1][c] = v.y; Bs[k + 2][c] = v.z; Bs[k + 3][c] = v.w;
        } else {
            int k = tid >> 4, c = (tid & 15) * 4;
            float4 v = *(const float4*)(B + (kt + k) * DD + col0 + c);
            Bs[k][c + 0] = v.x; Bs[k][c + 1] = v.y; Bs[k][c + 2] = v.z; Bs[k][c + 3] = v.w;
        }
        __syncthreads();
        #pragma unroll
        for (int kk = 0; kk < 16; kk++) {
            float a[4], b[4];
            #pragma unroll
            for (int i = 0; i < 4; i++) { a[i] = As[kk][ty * 4 + i]; b[i] = Bs[kk][tx * 4 + i]; }
            #pragma unroll
            for (int i = 0; i < 4; i++)
                #pragma unroll
                for (int j = 0; j < 4; j++)
                    acc[i][j] += a[i] * b[j];
        }
        __syncthreads();
    }
    #pragma unroll
    for (int i = 0; i < 4; i++)
        #pragma unroll
        for (int j = 0; j < 4; j++)
            Ch[(row0 + ty * 4 + i) * DD + col0 + tx * 4 + j] = __float2bfloat16(acc[i][j]);
}

// ---------------- h0 GEMM: 64x128 tile, 3 products, occ 2 -----------------------
#define STH_ELEMS 13824
#define A_PITCH 40
#define B_PITCH 136

__global__ __launch_bounds__(256, 2) void k_mma_h0(
    const bf16* __restrict__ Ah, const bf16* __restrict__ Al,
    const bf16* __restrict__ Bh, const bf16* __restrict__ Bl,
    const float* __restrict__ bias,
    bf16* __restrict__ Chi, bf16* __restrict__ Clo)
{
    extern __shared__ __align__(16) bf16 smem[];
    int tid = threadIdx.x;
    int lane = tid & 31, warp = tid >> 5;
    int wm = warp & 1, wn = warp >> 1;
    int row0 = blockIdx.y * 64, col0 = blockIdx.x * 128;

    uint sbase = (uint)__cvta_generic_to_shared(smem);
    int a_r0 = tid >> 2,        a_c0 = (tid & 3) * 8;
    int b_r0 = tid >> 4,        b_c0 = (tid & 15) * 8;
    int b_r1 = (tid + 256) >> 4;

    int ga0 = row0 + a_r0;
    uint sz0 = (ga0 < NN) ? 16u : 0u;
    int ca0 = (ga0 < NN) ? ga0 : 0;

    auto issue = [&](int st, int kt) {
        uint base = sbase + (uint)(st * STH_ELEMS) * 2u;
        uint dA0 = base + (uint)(a_r0 * A_PITCH + a_c0) * 2u;
        cp16z(dA0,            Ah + (size_t)ca0 * DD + kt + a_c0, sz0);
        cp16z(dA0 + 2560u*2u, Al + (size_t)ca0 * DD + kt + a_c0, sz0);
        uint dB0 = base + (5120u + (uint)(b_r0 * B_PITCH + b_c0)) * 2u;
        uint dB1 = base + (5120u + (uint)(b_r1 * B_PITCH + b_c0)) * 2u;
        cp16(dB0, Bh + (size_t)(kt + b_r0) * DD + col0 + b_c0);
        cp16(dB1, Bh + (size_t)(kt + b_r1) * DD + col0 + b_c0);
        cp16(dB0 + 4352u*2u, Bl + (size_t)(kt + b_r0) * DD + col0 + b_c0);
        cp16(dB1 + 4352u*2u, Bl + (size_t)(kt + b_r1) * DD + col0 + b_c0);
    };

    float acc[2][4][4] = {};
    issue(0, 0);   cp_commit();
    issue(1, 32);  cp_commit();

    #pragma unroll
    for (int i = 0; i < 8; i++) {
        if (i < 7) asm volatile("cp.async.wait_group 1;");
        else       asm volatile("cp.async.wait_group 0;");
        __syncthreads();
        if (i < 6) { issue((i + 2) % 3, (i + 2) * 32); cp_commit(); }

        int st = i % 3;
        uint base = sbase + (uint)(st * STH_ELEMS) * 2u;
        uint aAh = base, aAl = base + 2560u * 2u;
        uint aBh = base + 5120u * 2u, aBl = base + 9472u * 2u;

        #pragma unroll
        for (int ks = 0; ks < 32; ks += 16) {
            int arow = lane & 15;
            int kcol = ks + ((lane >> 4) << 3);
            uint ah[2][4], al[2][4];
            #pragma unroll
            for (int mi = 0; mi < 2; mi++) {
                uint off = (uint)((wm * 32 + mi * 16 + arow) * A_PITCH + kcol) * 2u;
                ldsm4(ah[mi][0], ah[mi][1], ah[mi][2], ah[mi][3], aAh + off);
                ldsm4(al[mi][0], al[mi][1], al[mi][2], al[mi][3], aAl + off);
            }
            uint bhf[2][4], blf[2][4];
            int brow = ks + (lane & 15);
            #pragma unroll
            for (int ng = 0; ng < 2; ng++) {
                int bcol = wn * 32 + ng * 16 + ((lane >> 4) << 3);
                uint off = (uint)(brow * B_PITCH + bcol) * 2u;
                ldsm4t(bhf[ng][0], bhf[ng][1], bhf[ng][2], bhf[ng][3], aBh + off);
                ldsm4t(blf[ng][0], blf[ng][1], blf[ng][2], blf[ng][3], aBl + off);
            }
            #pragma unroll
            for (int mi = 0; mi < 2; mi++)
                #pragma unroll
                for (int ng = 0; ng < 2; ng++) {
                    mma_bf16(acc[mi][ng * 2],     ah[mi], bhf[ng][0], bhf[ng][1]);
                    mma_bf16(acc[mi][ng * 2 + 1], ah[mi], bhf[ng][2], bhf[ng][3]);
                }
            #pragma unroll
            for (int mi = 0; mi < 2; mi++)
                #pragma unroll
                for (int ng = 0; ng < 2; ng++) {
                    mma_bf16(acc[mi][ng * 2],     al[mi], bhf[ng][0], bhf[ng][1]);
                    mma_bf16(acc[mi][ng * 2 + 1], al[mi], bhf[ng][2], bhf[ng][3]);
                }
            #pragma unroll
            for (int mi = 0; mi < 2; mi++)
                #pragma unroll
                for (int ng = 0; ng < 2; ng++) {
                    mma_bf16(acc[mi][ng * 2],     ah[mi], blf[ng][0], blf[ng][1]);
                    mma_bf16(acc[mi][ng * 2 + 1], ah[mi], blf[ng][2], blf[ng][3]);
                }
        }
    }

    int grp = lane >> 2, q = lane & 3;
    #pragma unroll
    for (int mi = 0; mi < 2; mi++) {
        int rb = row0 + wm * 32 + mi * 16 + grp;
        #pragma unroll
        for (int nj = 0; nj < 4; nj++) {
            int cb = col0 + wn * 32 + nj * 8 + q * 2;
            float b0 = bias[cb], b1 = bias[cb + 1];
            float v0 = fmaxf(acc[mi][nj][0] + b0, 0.f);
            float v1 = fmaxf(acc[mi][nj][1] + b1, 0.f);
            float v2 = fmaxf(acc[mi][nj][2] + b0, 0.f);
            float v3 = fmaxf(acc[mi][nj][3] + b1, 0.f);
            if (rb < NN) {
                size_t o = (size_t)rb * DD + cb;
                bf16 h0, l0, h1, l1;
                f32split(v0, h0, l0); f32split(v1, h1, l1);
                Chi[o] = h0; Chi[o + 1] = h1;
                Clo[o] = l0; Clo[o + 1] = l1;
            }
            if (rb + 8 < NN) {
                size_t o = (size_t)(rb + 8) * DD + cb;
                bf16 h2, l2, h3, l3;
                f32split(v2, h2, l2); f32split(v3, h3, l3);
                Chi[o] = h2; Chi[o + 1] = h3;
                Clo[o] = l2; Clo[o + 1] = l3;
            }
        }
    }
}

// ---------------- unified 2-product GEMM, 64x128 tile, occ 3 --------------------
#define STG_ELEMS 9472

__global__ __launch_bounds__(256, 3) void k_gemm(
    const bf16* __restrict__ Ah, const bf16* __restrict__ Al,
    const bf16* __restrict__ Bh,
    float* __restrict__ f32_out, const float* __restrict__ bias,
    const bf16* __restrict__ rhh, const bf16* __restrict__ rhl,
    bf16* __restrict__ Chi, bf16* __restrict__ Clo)
{
    extern __shared__ __align__(16) bf16 smem[];
    int col0 = blockIdx.x * 128;
    int row0 = blockIdx.y * 64;

    int tid = threadIdx.x;
    int lane = tid & 31, warp = tid >> 5;
    int wm = warp & 1, wn = warp >> 1;

    uint sbase = (uint)__cvta_generic_to_shared(smem);
    int a_r0 = tid >> 2,        a_c0 = (tid & 3) * 8;
    int b_r0 = tid >> 4,        b_c0 = (tid & 15) * 8;
    int b_r1 = (tid + 256) >> 4;

    int ga0 = row0 + a_r0;
    uint sz0 = (ga0 < NN) ? 16u : 0u;
    int ca0 = (ga0 < NN) ? ga0 : 0;

    auto issue = [&](int st, int kt) {
        uint base = sbase + (uint)(st * STG_ELEMS) * 2u;
        uint dA0 = base + (uint)(a_r0 * A_PITCH + a_c0) * 2u;
        cp16z(dA0,            Ah + (size_t)ca0 * DD + kt + a_c0, sz0);
        cp16z(dA0 + 2560u*2u, Al + (size_t)ca0 * DD + kt + a_c0, sz0);
        uint dB0 = base + (5120u + (uint)(b_r0 * B_PITCH + b_c0)) * 2u;
        uint dB1 = base + (5120u + (uint)(b_r1 * B_PITCH + b_c0)) * 2u;
        cp16(dB0, Bh + (size_t)(kt + b_r0) * DD + col0 + b_c0);
        cp16(dB1, Bh + (size_t)(kt + b_r1) * DD + col0 + b_c0);
    };

    float acc[2][4][4] = {};
    issue(0, 0);   cp_commit();
    issue(1, 32);  cp_commit();

    #pragma unroll
    for (int i = 0; i < 8; i++) {
        if (i < 7) asm volatile("cp.async.wait_group 1;");
        else       asm volatile("cp.async.wait_group 0;");
        __syncthreads();
        if (i < 6) { issue((i + 2) % 3, (i + 2) * 32); cp_commit(); }

        int st = i % 3;
        uint base = sbase + (uint)(st * STG_ELEMS) * 2u;
        uint aAh = base, aAl = base + 2560u * 2u;
        uint aBh = base + 5120u * 2u;

        #pragma unroll
        for (int ks = 0; ks < 32; ks += 16) {
            int arow = lane & 15;
            int kcol = ks + ((lane >> 4) << 3);
            uint ah[2][4], al[2][4];
            #pragma unroll
            for (int mi = 0; mi < 2; mi++) {
                uint off = (uint)((wm * 32 + mi * 16 + arow) * A_PITCH + kcol) * 2u;
                ldsm4(ah[mi][0], ah[mi][1], ah[mi][2], ah[mi][3], aAh + off);
                ldsm4(al[mi][0], al[mi][1], al[mi][2], al[mi][3], aAl + off);
            }
            uint bhf[2][4];
            int brow = ks + (lane & 15);
            #pragma unroll
            for (int ng = 0; ng < 2; ng++) {
                int bcol = wn * 32 + ng * 16 + ((lane >> 4) << 3);
                uint off = (uint)(brow * B_PITCH + bcol) * 2u;
                ldsm4t(bhf[ng][0], bhf[ng][1], bhf[ng][2], bhf[ng][3], aBh + off);
            }
            #pragma unroll
            for (int mi = 0; mi < 2; mi++)
                #pragma unroll
                for (int ng = 0; ng < 2; ng++) {
                    mma_bf16(acc[mi][ng * 2],     ah[mi], bhf[ng][0], bhf[ng][1]);
                    mma_bf16(acc[mi][ng * 2 + 1], ah[mi], bhf[ng][2], bhf[ng][3]);
                }
            #pragma unroll
            for (int mi = 0; mi < 2; mi++)
                #pragma unroll
                for (int ng = 0; ng < 2; ng++) {
                    mma_bf16(acc[mi][ng * 2],     al[mi], bhf[ng][0], bhf[ng][1]);
                    mma_bf16(acc[mi][ng * 2 + 1], al[mi], bhf[ng][2], bhf[ng][3]);
                }
        }
    }

    int grp = lane >> 2, q = lane & 3;
    #pragma unroll
    for (int mi = 0; mi < 2; mi++) {
        int rb = row0 + wm * 32 + mi * 16 + grp;
        #pragma unroll
        for (int nj = 0; nj < 4; nj++) {
            int cb = col0 + wn * 32 + nj * 8 + q * 2;
            float v0 = acc[mi][nj][0], v1 = acc[mi][nj][1];
            float v2 = acc[mi][nj][2], v3 = acc[mi][nj][3];
            if (bias) {
                float b0 = bias[cb], b1 = bias[cb + 1];
                size_t o0 = (size_t)rb * DD + cb;
                size_t o1 = (size_t)(rb + 8) * DD + cb;
                float r00 = 0.f, r01 = 0.f, r10 = 0.f, r11 = 0.f;
                if (rb < NN) {
                    float2 a2 = __bfloat1622float2(*(const __nv_bfloat162*)(rhh + o0));
                    float2 b2 = __bfloat1622float2(*(const __nv_bfloat162*)(rhl + o0));
                    r00 = a2.x + b2.x; r01 = a2.y + b2.y;
                }
                if (rb + 8 < NN) {
                    float2 a2 = __bfloat1622float2(*(const __nv_bfloat162*)(rhh + o1));
                    float2 b2 = __bfloat1622float2(*(const __nv_bfloat162*)(rhl + o1));
                    r10 = a2.x + b2.x; r11 = a2.y + b2.y;
                }
                v0 = fmaxf(v0 + b0 + r00, 0.f);
                v1 = fmaxf(v1 + b1 + r01, 0.f);
                v2 = fmaxf(v2 + b0 + r10, 0.f);
                v3 = fmaxf(v3 + b1 + r11, 0.f);
            }
            if (rb < NN) {
                size_t o = (size_t)rb * DD + cb;
                if (f32_out) { f32_out[o] = v0; f32_out[o + 1] = v1; }
                if (Chi) {
                    bf16 h0, l0, h1, l1;
                    f32split(v0, h0, l0); f32split(v1, h1, l1);
                    Chi[o] = h0; Chi[o + 1] = h1;
                    Clo[o] = l0; Clo[o + 1] = l1;
                }
            }
            if (rb + 8 < NN) {
                size_t o = (size_t)(rb + 8) * DD + cb;
                if (f32_out) { f32_out[o] = v2; f32_out[o + 1] = v3; }
                if (Chi) {
                    bf16 h2, l2, h3, l3;
                    f32split(v2, h2, l2); f32split(v3, h3, l3);
                    Chi[o] = h2; Chi[o + 1] = h3;
                    Clo[o] = l2; Clo[o + 1] = l3;
                }
            }
        }
    }
}

// ---------------- per-node online-softmax h-aggregation -------------------------
__global__ __launch_bounds__(256) void k_edge(
    const bf16* __restrict__ hhin,
    bf16* __restrict__ agg_hi, bf16* __restrict__ agg_lo)
{
    int gw = (blockIdx.x * blockDim.x + threadIdx.x) >> 5;
    int lane = threadIdx.x & 31;
    if (gw >= NN) return;
    int n = gw;
    int c0 = lane * 8;

    float t8[8];
    *(float4*)&t8[0] = *(const float4*)(g_t + (size_t)n * DD + c0);
    *(float4*)&t8[4] = *(const float4*)(g_t + (size_t)n * DD + c0 + 4);

    float m = -INFINITY, s = 0.f;
    float acc[8] = {};

    int e0 = g_off[n], e1 = g_off[n + 1];
    uint4 hv0, hv1;
    if (e0 < e1) {
        int sN = g_srcs[e0];
        hv0 = *(const uint4*)(hhin + (size_t)sN * DD + c0);
    }
    if (e0 + 1 < e1) {
        int sN = g_srcs[e0 + 1];
        hv1 = *(const uint4*)(hhin + (size_t)sN * DD + c0);
    }
    for (int e = e0; e < e1; e++) {
        uint4 hv = hv0;
        hv0 = hv1;
        if (e + 2 < e1) {
            int sN = g_srcs[e + 2];
            hv1 = *(const uint4*)(hhin + (size_t)sN * DD + c0);
        }

        const __nv_bfloat162* hp = (const __nv_bfloat162*)&hv;
        float hf[8];
        #pragma unroll
        for (int j = 0; j < 4; j++) {
            float2 f = __bfloat1622float2(hp[j]);
            hf[2 * j] = f.x; hf[2 * j + 1] = f.y;
        }
        float d = 0.f;
        #pragma unroll
        for (int j = 0; j < 8; j++) d += t8[j] * hf[j];
        #pragma unroll
        for (int o = 16; o > 0; o >>= 1) d += __shfl_xor_sync(0xffffffffu, d, o);
        d *= 0.0625f;

        float nm = fmaxf(m, d);
        float c = __expf(m - nm);
        float w = __expf(d - nm);
        s = s * c + w;
        m = nm;

        #pragma unroll
        for (int j = 0; j < 8; j++)
            acc[j] = acc[j] * c + w * hf[j];
    }

    float inv = 1.0f / (s + 1e-9f);
    bf16 hh8[8], hl8[8];
    #pragma unroll
    for (int j = 0; j < 8; j++) f32split(acc[j] * inv, hh8[j], hl8[j]);
    *(uint4*)(agg_hi + (size_t)n * DD + c0) = *(uint4*)&hh8[0];
    *(uint4*)(agg_lo + (size_t)n * DD + c0) = *(uint4*)&hl8[0];
}

// ---------------- launch ----------------------------------------------------------
extern "C" void kernel_launch(void* const* d_in, const int* in_sizes, int n_in,
                              void* d_out, int out_size)
{
    const float* x    = (const float*)d_in[0];
    const int*   edges= (const int*)  d_in[1];
    const float* w_in = (const float*)d_in[2];
    const float* b_in = (const float*)d_in[3];
    const float* wq   = (const float*)d_in[4];
    const float* wk   = (const float*)d_in[5];
    const float* wv   = (const float*)d_in[6];
    const float* wp   = (const float*)d_in[7];
    const float* bp   = (const float*)d_in[8];
    float* out = (float*)d_out;

    const int* src = edges;
    const int* dst = edges + NE;

    float *pt;
    bf16 *pxh, *pxl, *phhA, *phlA, *phhB, *phlB, *pwinh, *pwinl, *pMh, *pWh;
    cudaGetSymbolAddress((void**)&pt,    g_t);
    cudaGetSymbolAddress((void**)&pxh,   g_xh);
    cudaGetSymbolAddress((void**)&pxl,   g_xl);
    cudaGetSymbolAddress((void**)&phhA,  g_hhA);
    cudaGetSymbolAddress((void**)&phlA,  g_hlA);
    cudaGetSymbolAddress((void**)&phhB,  g_hhB);
    cudaGetSymbolAddress((void**)&phlB,  g_hlB);
    cudaGetSymbolAddress((void**)&pwinh, g_winh);
    cudaGetSymbolAddress((void**)&pwinl, g_winl);
    cudaGetSymbolAddress((void**)&pMh,   g_Mh);
    cudaGetSymbolAddress((void**)&pWh,   g_Wh);

    static cudaStream_t s_side = nullptr;
    static cudaEvent_t s_ev0 = nullptr, s_ev1 = nullptr;
    if (!s_side) {
        cudaFuncSetAttribute(k_mma_h0, cudaFuncAttributeMaxDynamicSharedMemorySize,
                             3 * STH_ELEMS * 2);
        cudaFuncSetAttribute(k_gemm, cudaFuncAttributeMaxDynamicSharedMemorySize,
                             3 * STG_ELEMS * 2);
        cudaStreamCreateWithFlags(&s_side, cudaStreamNonBlocking);
        cudaEventCreateWithFlags(&s_ev0, cudaEventDisableTiming);
        cudaEventCreateWithFlags(&s_ev1, cudaEventDisableTiming);
    }

    dim3 gw(2, 157);   // 64-row tiles: 157*64 = 10048 >= NN

    // ---- fork: weight folding + CSR build on side stream
    cudaEventRecord(s_ev0, 0);
    cudaStreamWaitEvent(s_side, s_ev0, 0);
    k_small    <<<dim3(4, 4, 6), 256, 0, s_side>>>(wq, wk, wv, wp, pMh, pWh);
    k_init     <<<(NN + 255) / 256, 256, 0, s_side>>>();
    k_hist     <<<(NE + 255) / 256, 256, 0, s_side>>>(dst);
    k_scan_part<<<40, 256, 0, s_side>>>();
    k_scan_top <<<1, 64, 0, s_side>>>();
    k_scan_add <<<40, 256, 0, s_side>>>();
    k_scatter  <<<(NE + 255) / 256, 256, 0, s_side>>>(src, dst);
    cudaEventRecord(s_ev1, s_side);

    // ---- main stream: conversions + h0 GEMM
    k_cvt2<<<(NN * DD + DD * DD + 255) / 256, 256>>>(
        x, pxh, pxl, NN * DD, w_in, pwinh, pwinl, DD * DD);
    k_mma_h0<<<gw, 256, 3 * STH_ELEMS * 2>>>(
        pxh, pxl, pwinh, pwinl, b_in, phhA, phlA);

    // join: t-GEMM needs pMh; edge needs CSR
    cudaStreamWaitEvent(0, s_ev1, 0);

    // agg buffers reuse x hi/lo (h0 already consumed them)
    bf16* paggh = pxh;
    bf16* paggl = pxl;

    bf16* chh = phhA; bf16* chl = phlA;
    bf16* nhh = phhB; bf16* nhl = phlB;
    for (int l = 0; l < NL; l++) {
        k_gemm<<<gw, 256, 3 * STG_ELEMS * 2>>>(
            chh, chl, pMh + l * DD * DD, pt,
            nullptr, nullptr, nullptr, nullptr, nullptr);
        // edge: aggregate h with softmax weights
        k_edge<<<(NN * 32 + 255) / 256, 256>>>(chh, paggh, paggl);
        // p GEMM: hnext = relu(agg @ wvp + bp + h)
        float* ho = (l == NL - 1) ? out : nullptr;
        bf16* oh = (l == NL - 1) ? nullptr : nhh;
        bf16* ol = (l == NL - 1) ? nullptr : nhl;
        k_gemm<<<gw, 256, 3 * STG_ELEMS * 2>>>(
            paggh, paggl, pWh + l * DD * DD, ho,
            bp + l * DD, chh, chl, oh, ol);
        bf16* t1 = chh; chh = nhh; nhh = t1;
        bf16* t2 = chl; chl = nhl; nhl = t2;
    }
}